// round 11
// baseline (speedup 1.0000x reference)
#include <cuda_runtime.h>
#include <cuda_fp16.h>

// Problem constants
#define Bn 8
#define Hn 64
#define Wn 2048
#define HWn (Hn * Wn)          // 131072
#define CHWn (4 * HWn)         // 524288

// Fused-kernel tile: 128x16 output, +-6 x / +-3 y halo for 3 iterations
#define TX 128
#define TY 16
#define EX 140
#define EY 22
#define NEXT (EX * EY)         // 3080
#define NTHREADS 384

// Setup-kernel tile
#define STY 8
#define SNT 256
#define SHX (TX + 4)           // 132
#define SHY (STY + 2)          // 10
#define SHALO (SHX * SHY)      // 1320

// Separable Gaussian weights: exp(-d^2/(2*0.9^2)) for d=1,2
#define W1f 0.53940751f
#define W4f 0.08465798f

// C2 = -1/(2*0.015^2) * log2(e)
#define C2f      (-3206.0005353f)
#define NEG2C2f  (6412.0010706f)
#define L2Ef     (1.4426950408889634f)
#define MASK_BIG (1.0e9f)
#define SKIP_THR (-40.0f)

#define SMEM_BYTES (2 * NEXT * (int)sizeof(uint2))   // 49280

// Iteration-invariant appearance data (allocation forbidden -> device globals)
__device__ unsigned char g_alive[Bn * HWn];
__device__ float         g_beta[Bn * HWn * 14];

// ---- helpers ----
__device__ __forceinline__ float ex2(float x) {
    float r;
    asm("ex2.approx.ftz.f32 %0, %1;" : "=f"(r) : "f"(x));
    return r;
}
__device__ __forceinline__ __half2 u2h(unsigned u) {
    __half2 h;
    *reinterpret_cast<unsigned*>(&h) = u;
    return h;
}
__device__ __forceinline__ unsigned h2u(__half2 h) {
    return *reinterpret_cast<unsigned*>(&h);
}
__device__ __forceinline__ float4 softmax4(float4 q) {
    const float mx = fmaxf(fmaxf(q.x, q.y), fmaxf(q.z, q.w));
    const float p0 = ex2((q.x - mx) * L2Ef);
    const float p1 = ex2((q.y - mx) * L2Ef);
    const float p2 = ex2((q.z - mx) * L2Ef);
    const float p3 = ex2((q.w - mx) * L2Ef);
    const float inv = __fdividef(1.0f, p0 + p1 + p2 + p3);
    return make_float4(p0 * inv, p1 * inv, p2 * inv, p3 * inv);
}

// ============================================================================
// Setup: per-pixel alive flag + (rare) exact beta taps. Iteration-invariant.
// ============================================================================
__global__ __launch_bounds__(SNT)
void crf_setup(const float* __restrict__ xyz,
               const float* __restrict__ mask)
{
    __shared__ float4 sG[SHALO];

    const int b   = blockIdx.z;
    const int ty0 = blockIdx.y * STY;
    const int tx0 = blockIdx.x * TX;
    const int tid = threadIdx.x;

    const float* __restrict__ Xb = xyz  + b * 3 * HWn;
    const float* __restrict__ Mb = mask + b * HWn;

    for (int i = tid; i < SHALO; i += SNT) {
        const int hy = i / SHX;
        const int hx = i - hy * SHX;
        const int gy = ty0 + hy - 1;
        const int gx = tx0 + hx - 2;
        float4 sg = make_float4(0.f, 0.f, 0.f, -MASK_BIG);
        if (gy >= 0 && gy < Hn && gx >= 0 && gx < Wn) {
            const int g = gy * Wn + gx;
            const float x = Xb[g];
            const float y = Xb[g + HWn];
            const float z = Xb[g + 2 * HWn];
            const float m = Mb[g];
            float nrm = x * x;
            nrm = fmaf(y, y, nrm);
            nrm = fmaf(z, z, nrm);
            sg.x = x; sg.y = y; sg.z = z;
            sg.w = fmaf(nrm, C2f, fmaf(m, MASK_BIG, -MASK_BIG));
        }
        sG[i] = sg;
    }
    __syncthreads();

    const int offs[14] = {
        -SHX - 2, -SHX - 1, -SHX, -SHX + 1, -SHX + 2,
               -2,       -1,            1,        2,
         SHX - 2,  SHX - 1,  SHX,  SHX + 1,  SHX + 2
    };

    for (int k = 0; k < (TX * STY) / SNT; ++k) {
        const int p  = tid + k * SNT;
        const int ty = p >> 7;
        const int tx = p & (TX - 1);
        const int base = (ty + 1) * SHX + (tx + 2);

        const float4 ga = sG[base];
        const float axs = ga.x * NEG2C2f;
        const float ays = ga.y * NEG2C2f;
        const float azs = ga.z * NEG2C2f;
        const float na  = ga.w;

        float maxa = -MASK_BIG;
        #pragma unroll
        for (int t = 0; t < 14; ++t) {
            const float4 gn = sG[base + offs[t]];
            const float arg = fmaf(gn.x, axs,
                              fmaf(gn.y, ays,
                              fmaf(gn.z, azs, gn.w + na)));
            maxa = fmaxf(maxa, arg);
        }

        const bool alive = (maxa > SKIP_THR) && (na > -1.0e8f);
        const int pix = b * HWn + (ty0 + ty) * Wn + (tx0 + tx);
        g_alive[pix] = alive ? 1 : 0;

        if (alive) {
            #pragma unroll
            for (int t = 0; t < 14; ++t) {
                const float4 gn = sG[base + offs[t]];
                const float arg = fmaf(gn.x, axs,
                                  fmaf(gn.y, ays,
                                  fmaf(gn.z, azs, gn.w + na)));
                g_beta[pix * 14 + t] = ex2(arg);
            }
        }
    }
}

// ============================================================================
// One CRF iteration: direct V-pass with in-thread row-folded H (no sH buffer).
// Update region: rows [IT+1, EY-1-IT), cols [2IT+2, EX-2-2IT), pair-processed.
// ============================================================================
template<int IT, bool LAST>
__device__ __forceinline__ void crf_do_iter(
    const uint2* __restrict__ sQin, uint2* __restrict__ sQout,
    const int b, const int ty0, const int tx0, const int tid,
    const float* __restrict__ unary, float* __restrict__ out,
    const __half2 w1h, const __half2 w4h,
    const __half2 wa01, const __half2 wa23,
    const __half2 ws01, const __half2 ws23,
    const __half2 ccA0, const __half2 ccA1, const __half2 ccA2, const __half2 ccA3,
    const __half2 ccB0, const __half2 ccB1, const __half2 ccB2, const __half2 ccB3)
{
    constexpr int HC0  = 2 * IT + 2;
    constexpr int HWID = EX - 4 - 4 * IT;   // 136 / 132 / 128
    constexpr int PP   = HWID / 2;          // 68 / 66 / 64 pairs per row
    constexpr int EP   = PP - 64;           // 4 / 2 / 0 extra pairs
    constexpr int LOG2EP = (EP == 4) ? 2 : 1;
    constexpr int UR0 = IT + 1, UR1 = EY - 1 - IT;

    auto u_pair = [&](int row, int col) {   // col even: pixels col, col+1
        const int c  = row * EX + col;
        const int gy = ty0 + row - 3;
        const int gx = tx0 + col - 6;       // even; pair never straddles W edge
        if (!LAST) {
            if (gy < 0 || gy >= Hn || gx < 0 || gx >= Wn) {
                *reinterpret_cast<uint4*>(&sQout[c]) = make_uint4(0u, 0u, 0u, 0u);
                return;
            }
        }
        const int g   = gy * Wn + gx;
        const int pix = b * HWn + g;
        const int gg  = b * CHWn + g;

        // 3x3 uint4 neighborhood (rows r-1,r,r+1; col groups c-2,c,c+2)
        const uint4 Am = *reinterpret_cast<const uint4*>(&sQin[c - EX - 2]);
        const uint4 Bm = *reinterpret_cast<const uint4*>(&sQin[c - EX]);
        const uint4 Cm = *reinterpret_cast<const uint4*>(&sQin[c - EX + 2]);
        const uint4 A0 = *reinterpret_cast<const uint4*>(&sQin[c - 2]);
        const uint4 B0 = *reinterpret_cast<const uint4*>(&sQin[c]);
        const uint4 C0 = *reinterpret_cast<const uint4*>(&sQin[c + 2]);
        const uint4 Ap = *reinterpret_cast<const uint4*>(&sQin[c + EX - 2]);
        const uint4 Bp = *reinterpret_cast<const uint4*>(&sQin[c + EX]);
        const uint4 Cp = *reinterpret_cast<const uint4*>(&sQin[c + EX + 2]);

        // Row fold: X' = W1*(X_up + X_dn) + X_mid  (exact by linearity)
        auto fold = [&](unsigned m, unsigned z, unsigned p) -> __half2 {
            return __hfma2(w1h, __hadd2(u2h(m), u2h(p)), u2h(z));
        };
        const __half2 Afx = fold(Am.x, A0.x, Ap.x);
        const __half2 Afy = fold(Am.y, A0.y, Ap.y);
        const __half2 Afz = fold(Am.z, A0.z, Ap.z);
        const __half2 Afw = fold(Am.w, A0.w, Ap.w);
        const __half2 Bfx = fold(Bm.x, B0.x, Bp.x);
        const __half2 Bfy = fold(Bm.y, B0.y, Bp.y);
        const __half2 Bfz = fold(Bm.z, B0.z, Bp.z);
        const __half2 Bfw = fold(Bm.w, B0.w, Bp.w);
        const __half2 Cfx = fold(Cm.x, C0.x, Cp.x);
        const __half2 Cfy = fold(Cm.y, C0.y, Cp.y);
        const __half2 Cfz = fold(Cm.z, C0.z, Cp.z);
        const __half2 Cfw = fold(Cm.w, C0.w, Cp.w);

        // 5-tap H on folded rows, minus raw center (hole)
        const __half2 sA01 = __hsub2(
            __hfma2(w4h, __hadd2(Afx, Cfx),
            __hfma2(w1h, __hadd2(Afz, Bfz), Bfx)), u2h(B0.x));
        const __half2 sA23 = __hsub2(
            __hfma2(w4h, __hadd2(Afy, Cfy),
            __hfma2(w1h, __hadd2(Afw, Bfw), Bfy)), u2h(B0.y));
        const __half2 sB01 = __hsub2(
            __hfma2(w4h, __hadd2(Afz, Cfz),
            __hfma2(w1h, __hadd2(Bfx, Cfx), Bfz)), u2h(B0.z));
        const __half2 sB23 = __hsub2(
            __hfma2(w4h, __hadd2(Afw, Cfw),
            __hfma2(w1h, __hadd2(Bfy, Cfy), Bfw)), u2h(B0.w));

        // alive flags for both pixels in one 16-bit load (pix even)
        const unsigned short al2 =
            *reinterpret_cast<const unsigned short*>(&g_alive[pix]);

        __half2 aA01 = __float2half2_rn(0.f), aA23 = aA01;
        __half2 aB01 = aA01, aB23 = aA01;
        if (al2) {
            const int offs[14] = {
                -EX - 2, -EX - 1, -EX, -EX + 1, -EX + 2,
                      -2,      -1,           1,       2,
                 EX - 2,  EX - 1,  EX,  EX + 1,  EX + 2
            };
            if (al2 & 0x00FFu) {
                const float* __restrict__ bp = g_beta + (size_t)pix * 14;
                #pragma unroll
                for (int t = 0; t < 14; ++t) {
                    const __half2 bmh = __float2half2_rn(bp[t]);
                    const uint2 q = sQin[c + offs[t]];
                    aA01 = __hfma2(bmh, u2h(q.x), aA01);
                    aA23 = __hfma2(bmh, u2h(q.y), aA23);
                }
            }
            if (al2 & 0xFF00u) {
                const float* __restrict__ bp = g_beta + (size_t)(pix + 1) * 14;
                #pragma unroll
                for (int t = 0; t < 14; ++t) {
                    const __half2 bmh = __float2half2_rn(bp[t]);
                    const uint2 q = sQin[c + 1 + offs[t]];
                    aB01 = __hfma2(bmh, u2h(q.x), aB01);
                    aB23 = __hfma2(bmh, u2h(q.y), aB23);
                }
            }
        }

        // Paired unary loads (gx even -> 8B aligned)
        const float2 u0  = *reinterpret_cast<const float2*>(&unary[gg]);
        const float2 u1  = *reinterpret_cast<const float2*>(&unary[gg + HWn]);
        const float2 u2v = *reinterpret_cast<const float2*>(&unary[gg + 2 * HWn]);
        const float2 u3  = *reinterpret_cast<const float2*>(&unary[gg + 3 * HWn]);

        float4 resA, resB;
        {
            const __half2 wk01 = __hmul2(sA01, __hfma2(wa01, aA01, ws01));
            const __half2 wk23 = __hmul2(sA23, __hfma2(wa23, aA23, ws23));
            __half2 pw01 = __hmul2(__low2half2(wk01), ccA0);
            pw01 = __hfma2(__high2half2(wk01), ccA1, pw01);
            pw01 = __hfma2(__low2half2(wk23),  ccA2, pw01);
            pw01 = __hfma2(__high2half2(wk23), ccA3, pw01);
            __half2 pw23 = __hmul2(__low2half2(wk01), ccB0);
            pw23 = __hfma2(__high2half2(wk01), ccB1, pw23);
            pw23 = __hfma2(__low2half2(wk23),  ccB2, pw23);
            pw23 = __hfma2(__high2half2(wk23), ccB3, pw23);
            const float2 p01 = __half22float2(pw01);
            const float2 p23 = __half22float2(pw23);
            resA = make_float4(u0.x - p01.x, u1.x - p01.y,
                               u2v.x - p23.x, u3.x - p23.y);
        }
        {
            const __half2 wk01 = __hmul2(sB01, __hfma2(wa01, aB01, ws01));
            const __half2 wk23 = __hmul2(sB23, __hfma2(wa23, aB23, ws23));
            __half2 pw01 = __hmul2(__low2half2(wk01), ccA0);
            pw01 = __hfma2(__high2half2(wk01), ccA1, pw01);
            pw01 = __hfma2(__low2half2(wk23),  ccA2, pw01);
            pw01 = __hfma2(__high2half2(wk23), ccA3, pw01);
            __half2 pw23 = __hmul2(__low2half2(wk01), ccB0);
            pw23 = __hfma2(__high2half2(wk01), ccB1, pw23);
            pw23 = __hfma2(__low2half2(wk23),  ccB2, pw23);
            pw23 = __hfma2(__high2half2(wk23), ccB3, pw23);
            const float2 p01 = __half22float2(pw01);
            const float2 p23 = __half22float2(pw23);
            resB = make_float4(u0.y - p01.x, u1.y - p01.y,
                               u2v.y - p23.x, u3.y - p23.y);
        }

        if (LAST) {
            *reinterpret_cast<float2*>(&out[gg])           = make_float2(resA.x, resB.x);
            *reinterpret_cast<float2*>(&out[gg + HWn])     = make_float2(resA.y, resB.y);
            *reinterpret_cast<float2*>(&out[gg + 2 * HWn]) = make_float2(resA.z, resB.z);
            *reinterpret_cast<float2*>(&out[gg + 3 * HWn]) = make_float2(resA.w, resB.w);
        } else {
            const float4 smA = softmax4(resA);
            const float4 smB = softmax4(resB);
            *reinterpret_cast<uint4*>(&sQout[c]) =
                make_uint4(h2u(__floats2half2_rn(smA.x, smA.y)),
                           h2u(__floats2half2_rn(smA.z, smA.w)),
                           h2u(__floats2half2_rn(smB.x, smB.y)),
                           h2u(__floats2half2_rn(smB.z, smB.w)));
        }
    };

    {
        const int px = tid & 63;
        for (int r = UR0 + (tid >> 6); r < UR1; r += NTHREADS >> 6)
            u_pair(r, HC0 + 2 * px);
        if (EP > 0) {
            const int px2 = 64 + (tid & (EP - 1));
            const int r = UR0 + (tid >> LOG2EP);
            if (r < UR1) u_pair(r, HC0 + 2 * px2);
        }
    }
    if (!LAST) __syncthreads();
}

// ============================================================================
// Fused kernel: 3 CRF iterations, Q in fp16 smem, 2-buffer ping-pong, 3 syncs.
// ============================================================================
__global__ __launch_bounds__(NTHREADS, 4)
void crf_fused(const float* __restrict__ unary,
               const float* __restrict__ wapp,
               const float* __restrict__ wsmo,
               const float* __restrict__ compat,
               float*       __restrict__ out)
{
    extern __shared__ uint2 smem[];
    uint2* sA = smem;
    uint2* sB = smem + NEXT;

    const int b   = blockIdx.z;
    const int ty0 = blockIdx.y * TY;
    const int tx0 = blockIdx.x * TX;
    const int tid = threadIdx.x;

    // Uniform parameters -> packed half2
    const __half2 w1h  = __float2half2_rn(W1f);
    const __half2 w4h  = __float2half2_rn(W4f);
    const __half2 wa01 = __floats2half2_rn(wapp[0], wapp[1]);
    const __half2 wa23 = __floats2half2_rn(wapp[2], wapp[3]);
    const __half2 ws01 = __floats2half2_rn(wsmo[0], wsmo[1]);
    const __half2 ws23 = __floats2half2_rn(wsmo[2], wsmo[3]);
    const __half2 ccA0 = __floats2half2_rn(compat[0],  compat[4]);
    const __half2 ccA1 = __floats2half2_rn(compat[1],  compat[5]);
    const __half2 ccA2 = __floats2half2_rn(compat[2],  compat[6]);
    const __half2 ccA3 = __floats2half2_rn(compat[3],  compat[7]);
    const __half2 ccB0 = __floats2half2_rn(compat[8],  compat[12]);
    const __half2 ccB1 = __floats2half2_rn(compat[9],  compat[13]);
    const __half2 ccB2 = __floats2half2_rn(compat[10], compat[14]);
    const __half2 ccB3 = __floats2half2_rn(compat[11], compat[15]);

    // ---- Phase 0: softmax(unary) over the full extended tile -> sA ----
    for (int i = tid; i < NEXT; i += NTHREADS) {
        const int row = i / EX;
        const int col = i - row * EX;
        const int gy = ty0 + row - 3;
        const int gx = tx0 + col - 6;
        uint2 q = make_uint2(0u, 0u);
        if (gy >= 0 && gy < Hn && gx >= 0 && gx < Wn) {
            const int gg = b * CHWn + gy * Wn + gx;
            const float4 sm = softmax4(make_float4(unary[gg],
                                                   unary[gg + HWn],
                                                   unary[gg + 2 * HWn],
                                                   unary[gg + 3 * HWn]));
            q = make_uint2(h2u(__floats2half2_rn(sm.x, sm.y)),
                           h2u(__floats2half2_rn(sm.z, sm.w)));
        }
        sA[i] = q;
    }
    __syncthreads();

    crf_do_iter<0, false>(sA, sB, b, ty0, tx0, tid, unary, out,
                          w1h, w4h, wa01, wa23, ws01, ws23,
                          ccA0, ccA1, ccA2, ccA3, ccB0, ccB1, ccB2, ccB3);
    crf_do_iter<1, false>(sB, sA, b, ty0, tx0, tid, unary, out,
                          w1h, w4h, wa01, wa23, ws01, ws23,
                          ccA0, ccA1, ccA2, ccA3, ccB0, ccB1, ccB2, ccB3);
    crf_do_iter<2, true >(sA, sB, b, ty0, tx0, tid, unary, out,
                          w1h, w4h, wa01, wa23, ws01, ws23,
                          ccA0, ccA1, ccA2, ccA3, ccB0, ccB1, ccB2, ccB3);
}

extern "C" void kernel_launch(void* const* d_in, const int* in_sizes, int n_in,
                              void* d_out, int out_size)
{
    const float* unary  = (const float*)d_in[0];
    const float* xyz    = (const float*)d_in[1];
    const float* mask   = (const float*)d_in[2];
    const float* wapp   = (const float*)d_in[3];
    const float* wsmo   = (const float*)d_in[4];
    const float* compat = (const float*)d_in[5];
    float* out = (float*)d_out;

    cudaFuncSetAttribute(crf_fused, cudaFuncAttributeMaxDynamicSharedMemorySize,
                         SMEM_BYTES);

    dim3 sgrid(Wn / TX, Hn / STY, Bn);
    crf_setup<<<sgrid, SNT>>>(xyz, mask);

    dim3 grid(Wn / TX, Hn / TY, Bn);
    crf_fused<<<grid, NTHREADS, SMEM_BYTES>>>(unary, wapp, wsmo, compat, out);
}

// round 12
// speedup vs baseline: 1.8714x; 1.8714x over previous
#include <cuda_runtime.h>
#include <cuda_fp16.h>

// Problem constants
#define Bn 8
#define Hn 64
#define Wn 2048
#define HWn (Hn * Wn)          // 131072
#define CHWn (4 * HWn)         // 524288

// Fused-kernel tile: 128x16 output, +-6 x / +-3 y halo for 3 iterations
#define TX 128
#define TY 16
#define EX 140
#define EY 22
#define NEXT (EX * EY)         // 3080
#define NTHREADS 512

// Setup-kernel tile
#define STY 8
#define SNT 256
#define SHX (TX + 4)           // 132
#define SHY (STY + 2)          // 10
#define SHALO (SHX * SHY)      // 1320

// Separable Gaussian weights: exp(-d^2/(2*0.9^2)) for d=1,2
#define W1f 0.53940751f
#define W4f 0.08465798f

// C2 = -1/(2*0.015^2) * log2(e)
#define C2f      (-3206.0005353f)
#define NEG2C2f  (6412.0010706f)
#define L2Ef     (1.4426950408889634f)
#define MASK_BIG (1.0e9f)
#define SKIP_THR (-40.0f)

#define SMEM_BYTES (3 * NEXT * (int)sizeof(uint2))   // 73920

// Iteration-invariant appearance data (allocation forbidden -> device globals)
__device__ unsigned char g_alive[Bn * HWn];
__device__ float         g_beta[Bn * HWn * 14];

// ---- helpers ----
__device__ __forceinline__ float ex2(float x) {
    float r;
    asm("ex2.approx.ftz.f32 %0, %1;" : "=f"(r) : "f"(x));
    return r;
}
__device__ __forceinline__ __half2 u2h(unsigned u) {
    __half2 h;
    *reinterpret_cast<unsigned*>(&h) = u;
    return h;
}
__device__ __forceinline__ unsigned h2u(__half2 h) {
    return *reinterpret_cast<unsigned*>(&h);
}
// Softmax without max-subtraction: |q| <= ~8 here, far from fp32 exp2 limits.
__device__ __forceinline__ float4 softmax4(float4 q) {
    const float p0 = ex2(q.x * L2Ef);
    const float p1 = ex2(q.y * L2Ef);
    const float p2 = ex2(q.z * L2Ef);
    const float p3 = ex2(q.w * L2Ef);
    const float inv = __fdividef(1.0f, p0 + p1 + p2 + p3);
    return make_float4(p0 * inv, p1 * inv, p2 * inv, p3 * inv);
}

// ============================================================================
// Setup: per-pixel alive flag + (rare) exact beta taps. Iteration-invariant.
// ============================================================================
__global__ __launch_bounds__(SNT)
void crf_setup(const float* __restrict__ xyz,
               const float* __restrict__ mask)
{
    __shared__ float4 sG[SHALO];

    const int b   = blockIdx.z;
    const int ty0 = blockIdx.y * STY;
    const int tx0 = blockIdx.x * TX;
    const int tid = threadIdx.x;

    const float* __restrict__ Xb = xyz  + b * 3 * HWn;
    const float* __restrict__ Mb = mask + b * HWn;

    for (int i = tid; i < SHALO; i += SNT) {
        const int hy = i / SHX;
        const int hx = i - hy * SHX;
        const int gy = ty0 + hy - 1;
        const int gx = tx0 + hx - 2;
        float4 sg = make_float4(0.f, 0.f, 0.f, -MASK_BIG);
        if (gy >= 0 && gy < Hn && gx >= 0 && gx < Wn) {
            const int g = gy * Wn + gx;
            const float x = Xb[g];
            const float y = Xb[g + HWn];
            const float z = Xb[g + 2 * HWn];
            const float m = Mb[g];
            float nrm = x * x;
            nrm = fmaf(y, y, nrm);
            nrm = fmaf(z, z, nrm);
            sg.x = x; sg.y = y; sg.z = z;
            sg.w = fmaf(nrm, C2f, fmaf(m, MASK_BIG, -MASK_BIG));
        }
        sG[i] = sg;
    }
    __syncthreads();

    const int offs[14] = {
        -SHX - 2, -SHX - 1, -SHX, -SHX + 1, -SHX + 2,
               -2,       -1,            1,        2,
         SHX - 2,  SHX - 1,  SHX,  SHX + 1,  SHX + 2
    };

    for (int k = 0; k < (TX * STY) / SNT; ++k) {
        const int p  = tid + k * SNT;
        const int ty = p >> 7;
        const int tx = p & (TX - 1);
        const int base = (ty + 1) * SHX + (tx + 2);

        const float4 ga = sG[base];
        const float axs = ga.x * NEG2C2f;
        const float ays = ga.y * NEG2C2f;
        const float azs = ga.z * NEG2C2f;
        const float na  = ga.w;

        float maxa = -MASK_BIG;
        #pragma unroll
        for (int t = 0; t < 14; ++t) {
            const float4 gn = sG[base + offs[t]];
            const float arg = fmaf(gn.x, axs,
                              fmaf(gn.y, ays,
                              fmaf(gn.z, azs, gn.w + na)));
            maxa = fmaxf(maxa, arg);
        }

        const bool alive = (maxa > SKIP_THR) && (na > -1.0e8f);
        const int pix = b * HWn + (ty0 + ty) * Wn + (tx0 + tx);
        g_alive[pix] = alive ? 1 : 0;

        if (alive) {
            #pragma unroll
            for (int t = 0; t < 14; ++t) {
                const float4 gn = sG[base + offs[t]];
                const float arg = fmaf(gn.x, axs,
                                  fmaf(gn.y, ays,
                                  fmaf(gn.z, azs, gn.w + na)));
                g_beta[pix * 14 + t] = ex2(arg);
            }
        }
    }
}

// ============================================================================
// One in-smem CRF iteration (fp16 storage, paired H-pass, scalar V-pass).
// ============================================================================
template<int IT, bool LAST>
__device__ __forceinline__ void crf_do_iter(
    const uint2* __restrict__ sQin, uint2* __restrict__ sQout,
    uint2* __restrict__ sH,
    const int b, const int ty0, const int tx0, const int tid,
    const float* __restrict__ unary, float* __restrict__ out,
    const __half2 w1h, const __half2 w4h,
    const __half2 wa01, const __half2 wa23,
    const __half2 ws01, const __half2 ws23,
    const __half2 ccA0, const __half2 ccA1, const __half2 ccA2, const __half2 ccA3,
    const __half2 ccB0, const __half2 ccB1, const __half2 ccB2, const __half2 ccB3)
{
    constexpr int HR0 = IT, HR1 = EY - IT;
    constexpr int HC0 = 2 * IT + 2;
    constexpr int HWID = EX - 4 - 4 * IT;   // 136 / 132 / 128
    constexpr int PP   = HWID / 2;          // 68 / 66 / 64 pairs per row
    constexpr int EP   = PP - 64;           // 4 / 2 / 0 extra pairs
    constexpr int LOG2EP = (EP == 4) ? 2 : 1;
    constexpr int EXTRA = HWID - 128;       // 8 / 4 / 0 (scalar V extra cols)
    constexpr int SHV   = (EXTRA == 8) ? 3 : 2;
    constexpr int UR0 = IT + 1, UR1 = EY - 1 - IT;

    // ---- Horizontal 5-tap pass on point pairs (small live set, no spill) ----
    auto h_pair = [&](int c) {   // c even: points c, c+1
        const uint4 A = *reinterpret_cast<const uint4*>(&sQin[c - 2]);
        const uint4 B = *reinterpret_cast<const uint4*>(&sQin[c]);
        const uint4 C = *reinterpret_cast<const uint4*>(&sQin[c + 2]);
        const __half2 h00 = __hfma2(w4h, __hadd2(u2h(A.x), u2h(C.x)),
                            __hfma2(w1h, __hadd2(u2h(A.z), u2h(B.z)), u2h(B.x)));
        const __half2 h01 = __hfma2(w4h, __hadd2(u2h(A.y), u2h(C.y)),
                            __hfma2(w1h, __hadd2(u2h(A.w), u2h(B.w)), u2h(B.y)));
        const __half2 h10 = __hfma2(w4h, __hadd2(u2h(A.z), u2h(C.z)),
                            __hfma2(w1h, __hadd2(u2h(B.x), u2h(C.x)), u2h(B.z)));
        const __half2 h11 = __hfma2(w4h, __hadd2(u2h(A.w), u2h(C.w)),
                            __hfma2(w1h, __hadd2(u2h(B.y), u2h(C.y)), u2h(B.w)));
        *reinterpret_cast<uint4*>(&sH[c]) =
            make_uint4(h2u(h00), h2u(h01), h2u(h10), h2u(h11));
    };

    {
        const int px = tid & 63;
        for (int r = HR0 + (tid >> 6); r < HR1; r += NTHREADS >> 6)
            h_pair(r * EX + HC0 + 2 * px);
        if (EP > 0) {
            const int px2 = 64 + (tid & (EP - 1));
            const int r = HR0 + (tid >> LOG2EP);
            if (r < HR1) h_pair(r * EX + HC0 + 2 * px2);
        }
    }
    __syncthreads();

    // ---- Vertical 3-tap + update (scalar per point, R9-proven) ----
    auto u_point = [&](int row, int col) {
        const int c  = row * EX + col;
        const int gy = ty0 + row - 3;
        const int gx = tx0 + col - 6;
        if (!LAST) {
            if (gy < 0 || gy >= Hn || gx < 0 || gx >= Wn) {
                sQout[c] = make_uint2(0u, 0u);
                return;
            }
        }
        const int g   = gy * Wn + gx;
        const int pix = b * HWn + g;
        const int gg  = b * CHWn + g;

        const unsigned char alive = g_alive[pix];

        const uint2 hm = sH[c - EX];
        const uint2 h0 = sH[c];
        const uint2 hp = sH[c + EX];
        const uint2 qc = sQin[c];

        // S = H0 + W1*(Hm+Hp) - Qc
        const __half2 s01 = __hsub2(
            __hfma2(w1h, __hadd2(u2h(hm.x), u2h(hp.x)), u2h(h0.x)), u2h(qc.x));
        const __half2 s23 = __hsub2(
            __hfma2(w1h, __hadd2(u2h(hm.y), u2h(hp.y)), u2h(h0.y)), u2h(qc.y));

        __half2 a01 = __float2half2_rn(0.f);
        __half2 a23 = a01;
        if (alive) {
            const float* __restrict__ bp = g_beta + (size_t)pix * 14;
            const int offs[14] = {
                -EX - 2, -EX - 1, -EX, -EX + 1, -EX + 2,
                      -2,      -1,           1,       2,
                 EX - 2,  EX - 1,  EX,  EX + 1,  EX + 2
            };
            #pragma unroll
            for (int t = 0; t < 14; ++t) {
                const __half2 bmh = __float2half2_rn(bp[t]);
                const uint2 q = sQin[c + offs[t]];
                a01 = __hfma2(bmh, u2h(q.x), a01);
                a23 = __hfma2(bmh, u2h(q.y), a23);
            }
        }

        const __half2 wk01 = __hmul2(s01, __hfma2(wa01, a01, ws01));
        const __half2 wk23 = __hmul2(s23, __hfma2(wa23, a23, ws23));

        __half2 pw01 = __hmul2(__low2half2(wk01), ccA0);
        pw01 = __hfma2(__high2half2(wk01), ccA1, pw01);
        pw01 = __hfma2(__low2half2(wk23),  ccA2, pw01);
        pw01 = __hfma2(__high2half2(wk23), ccA3, pw01);
        __half2 pw23 = __hmul2(__low2half2(wk01), ccB0);
        pw23 = __hfma2(__high2half2(wk01), ccB1, pw23);
        pw23 = __hfma2(__low2half2(wk23),  ccB2, pw23);
        pw23 = __hfma2(__high2half2(wk23), ccB3, pw23);

        const float2 p01 = __half22float2(pw01);
        const float2 p23 = __half22float2(pw23);

        const float r0 = unary[gg]           - p01.x;
        const float r1 = unary[gg + HWn]     - p01.y;
        const float r2 = unary[gg + 2 * HWn] - p23.x;
        const float r3 = unary[gg + 3 * HWn] - p23.y;

        if (LAST) {
            out[gg]           = r0;
            out[gg + HWn]     = r1;
            out[gg + 2 * HWn] = r2;
            out[gg + 3 * HWn] = r3;
        } else {
            const float4 sm = softmax4(make_float4(r0, r1, r2, r3));
            sQout[c] = make_uint2(h2u(__floats2half2_rn(sm.x, sm.y)),
                                  h2u(__floats2half2_rn(sm.z, sm.w)));
        }
    };

    {
        const int cx = tid & 127;
        for (int r = UR0 + (tid >> 7); r < UR1; r += NTHREADS >> 7)
            u_point(r, HC0 + cx);
        if (EXTRA > 0) {
            const int cx2 = 128 + (tid & (EXTRA - 1));
            const int r = UR0 + (tid >> SHV);
            if (r < UR1) u_point(r, HC0 + cx2);
        }
    }
    if (!LAST) __syncthreads();
}

// ============================================================================
// Fused kernel: 3 CRF iterations, Q in fp16 smem, ping-pong buffers.
// ============================================================================
__global__ __launch_bounds__(NTHREADS, 3)
void crf_fused(const float* __restrict__ unary,
               const float* __restrict__ wapp,
               const float* __restrict__ wsmo,
               const float* __restrict__ compat,
               float*       __restrict__ out)
{
    extern __shared__ uint2 smem[];
    uint2* sA = smem;
    uint2* sB = smem + NEXT;
    uint2* sH = smem + 2 * NEXT;

    const int b   = blockIdx.z;
    const int ty0 = blockIdx.y * TY;
    const int tx0 = blockIdx.x * TX;
    const int tid = threadIdx.x;

    // Uniform parameters -> packed half2
    const __half2 w1h  = __float2half2_rn(W1f);
    const __half2 w4h  = __float2half2_rn(W4f);
    const __half2 wa01 = __floats2half2_rn(wapp[0], wapp[1]);
    const __half2 wa23 = __floats2half2_rn(wapp[2], wapp[3]);
    const __half2 ws01 = __floats2half2_rn(wsmo[0], wsmo[1]);
    const __half2 ws23 = __floats2half2_rn(wsmo[2], wsmo[3]);
    const __half2 ccA0 = __floats2half2_rn(compat[0],  compat[4]);
    const __half2 ccA1 = __floats2half2_rn(compat[1],  compat[5]);
    const __half2 ccA2 = __floats2half2_rn(compat[2],  compat[6]);
    const __half2 ccA3 = __floats2half2_rn(compat[3],  compat[7]);
    const __half2 ccB0 = __floats2half2_rn(compat[8],  compat[12]);
    const __half2 ccB1 = __floats2half2_rn(compat[9],  compat[13]);
    const __half2 ccB2 = __floats2half2_rn(compat[10], compat[14]);
    const __half2 ccB3 = __floats2half2_rn(compat[11], compat[15]);

    // ---- Phase 0: softmax(unary) over the full extended tile -> sA ----
    for (int i = tid; i < NEXT; i += NTHREADS) {
        const int row = i / EX;
        const int col = i - row * EX;
        const int gy = ty0 + row - 3;
        const int gx = tx0 + col - 6;
        uint2 q = make_uint2(0u, 0u);
        if (gy >= 0 && gy < Hn && gx >= 0 && gx < Wn) {
            const int gg = b * CHWn + gy * Wn + gx;
            const float4 sm = softmax4(make_float4(unary[gg],
                                                   unary[gg + HWn],
                                                   unary[gg + 2 * HWn],
                                                   unary[gg + 3 * HWn]));
            q = make_uint2(h2u(__floats2half2_rn(sm.x, sm.y)),
                           h2u(__floats2half2_rn(sm.z, sm.w)));
        }
        sA[i] = q;
    }
    __syncthreads();

    crf_do_iter<0, false>(sA, sB, sH, b, ty0, tx0, tid, unary, out,
                          w1h, w4h, wa01, wa23, ws01, ws23,
                          ccA0, ccA1, ccA2, ccA3, ccB0, ccB1, ccB2, ccB3);
    crf_do_iter<1, false>(sB, sA, sH, b, ty0, tx0, tid, unary, out,
                          w1h, w4h, wa01, wa23, ws01, ws23,
                          ccA0, ccA1, ccA2, ccA3, ccB0, ccB1, ccB2, ccB3);
    crf_do_iter<2, true >(sA, sB, sH, b, ty0, tx0, tid, unary, out,
                          w1h, w4h, wa01, wa23, ws01, ws23,
                          ccA0, ccA1, ccA2, ccA3, ccB0, ccB1, ccB2, ccB3);
}

extern "C" void kernel_launch(void* const* d_in, const int* in_sizes, int n_in,
                              void* d_out, int out_size)
{
    const float* unary  = (const float*)d_in[0];
    const float* xyz    = (const float*)d_in[1];
    const float* mask   = (const float*)d_in[2];
    const float* wapp   = (const float*)d_in[3];
    const float* wsmo   = (const float*)d_in[4];
    const float* compat = (const float*)d_in[5];
    float* out = (float*)d_out;

    cudaFuncSetAttribute(crf_fused, cudaFuncAttributeMaxDynamicSharedMemorySize,
                         SMEM_BYTES);

    dim3 sgrid(Wn / TX, Hn / STY, Bn);
    crf_setup<<<sgrid, SNT>>>(xyz, mask);

    dim3 grid(Wn / TX, Hn / TY, Bn);
    crf_fused<<<grid, NTHREADS, SMEM_BYTES>>>(unary, wapp, wsmo, compat, out);
}

// round 13
// speedup vs baseline: 1.8819x; 1.0056x over previous
#include <cuda_runtime.h>
#include <cuda_fp16.h>

// Problem constants
#define Bn 8
#define Hn 64
#define Wn 2048
#define HWn (Hn * Wn)          // 131072
#define CHWn (4 * HWn)         // 524288

// Fused-kernel tile: 128x16 output, +-6 x / +-3 y halo for 3 iterations
#define TX 128
#define TY 16
#define EX 140
#define EY 22
#define NEXT (EX * EY)         // 3080
#define NTHREADS 512

// Setup-kernel tile (single-iteration halo), fattened to cut halo redundancy
#define STY 16
#define SNT 256
#define SHX (TX + 4)           // 132
#define SHY (STY + 2)          // 18
#define SHALO (SHX * SHY)      // 2376

// Separable Gaussian weights: exp(-d^2/(2*0.9^2)) for d=1,2
#define W1f 0.53940751f
#define W4f 0.08465798f

// C2 = -1/(2*0.015^2) * log2(e)
#define C2f      (-3206.0005353f)
#define NEG2C2f  (6412.0010706f)
#define L2Ef     (1.4426950408889634f)
#define MASK_BIG (1.0e9f)
#define SKIP_THR (-40.0f)

#define SMEM_BYTES (3 * NEXT * (int)sizeof(uint2))   // 73920

// Iteration-invariant appearance data (allocation forbidden -> device globals)
__device__ unsigned char g_alive[Bn * HWn];
__device__ float         g_beta[Bn * HWn * 14];

// ---- helpers ----
__device__ __forceinline__ float ex2(float x) {
    float r;
    asm("ex2.approx.ftz.f32 %0, %1;" : "=f"(r) : "f"(x));
    return r;
}
__device__ __forceinline__ __half2 u2h(unsigned u) {
    __half2 h;
    *reinterpret_cast<unsigned*>(&h) = u;
    return h;
}
__device__ __forceinline__ unsigned h2u(__half2 h) {
    return *reinterpret_cast<unsigned*>(&h);
}
// Softmax without max-subtraction: |q| <= ~8 here, far from fp32 exp2 limits.
__device__ __forceinline__ float4 softmax4(float4 q) {
    const float p0 = ex2(q.x * L2Ef);
    const float p1 = ex2(q.y * L2Ef);
    const float p2 = ex2(q.z * L2Ef);
    const float p3 = ex2(q.w * L2Ef);
    const float inv = __fdividef(1.0f, p0 + p1 + p2 + p3);
    return make_float4(p0 * inv, p1 * inv, p2 * inv, p3 * inv);
}

// ============================================================================
// Setup: per-pixel alive flag + (rare) exact beta taps. Iteration-invariant.
// ============================================================================
__global__ __launch_bounds__(SNT)
void crf_setup(const float* __restrict__ xyz,
               const float* __restrict__ mask)
{
    __shared__ float4 sG[SHALO];

    const int b   = blockIdx.z;
    const int ty0 = blockIdx.y * STY;
    const int tx0 = blockIdx.x * TX;
    const int tid = threadIdx.x;

    const float* __restrict__ Xb = xyz  + b * 3 * HWn;
    const float* __restrict__ Mb = mask + b * HWn;

    for (int i = tid; i < SHALO; i += SNT) {
        const int hy = i / SHX;
        const int hx = i - hy * SHX;
        const int gy = ty0 + hy - 1;
        const int gx = tx0 + hx - 2;
        float4 sg = make_float4(0.f, 0.f, 0.f, -MASK_BIG);
        if (gy >= 0 && gy < Hn && gx >= 0 && gx < Wn) {
            const int g = gy * Wn + gx;
            const float x = Xb[g];
            const float y = Xb[g + HWn];
            const float z = Xb[g + 2 * HWn];
            const float m = Mb[g];
            float nrm = x * x;
            nrm = fmaf(y, y, nrm);
            nrm = fmaf(z, z, nrm);
            sg.x = x; sg.y = y; sg.z = z;
            sg.w = fmaf(nrm, C2f, fmaf(m, MASK_BIG, -MASK_BIG));
        }
        sG[i] = sg;
    }
    __syncthreads();

    const int offs[14] = {
        -SHX - 2, -SHX - 1, -SHX, -SHX + 1, -SHX + 2,
               -2,       -1,            1,        2,
         SHX - 2,  SHX - 1,  SHX,  SHX + 1,  SHX + 2
    };

    for (int k = 0; k < (TX * STY) / SNT; ++k) {
        const int p  = tid + k * SNT;
        const int ty = p >> 7;
        const int tx = p & (TX - 1);
        const int base = (ty + 1) * SHX + (tx + 2);

        const float4 ga = sG[base];
        const float axs = ga.x * NEG2C2f;
        const float ays = ga.y * NEG2C2f;
        const float azs = ga.z * NEG2C2f;
        const float na  = ga.w;

        float maxa = -MASK_BIG;
        #pragma unroll
        for (int t = 0; t < 14; ++t) {
            const float4 gn = sG[base + offs[t]];
            const float arg = fmaf(gn.x, axs,
                              fmaf(gn.y, ays,
                              fmaf(gn.z, azs, gn.w + na)));
            maxa = fmaxf(maxa, arg);
        }

        const bool alive = (maxa > SKIP_THR) && (na > -1.0e8f);
        const int pix = b * HWn + (ty0 + ty) * Wn + (tx0 + tx);
        g_alive[pix] = alive ? 1 : 0;

        if (alive) {
            #pragma unroll
            for (int t = 0; t < 14; ++t) {
                const float4 gn = sG[base + offs[t]];
                const float arg = fmaf(gn.x, axs,
                                  fmaf(gn.y, ays,
                                  fmaf(gn.z, azs, gn.w + na)));
                g_beta[pix * 14 + t] = ex2(arg);
            }
        }
    }
}

// ============================================================================
// One in-smem CRF iteration (fp16 storage, paired H-pass, scalar V-pass).
// ============================================================================
template<int IT, bool LAST>
__device__ __forceinline__ void crf_do_iter(
    const uint2* __restrict__ sQin, uint2* __restrict__ sQout,
    uint2* __restrict__ sH,
    const int b, const int ty0, const int tx0, const int tid,
    const float* __restrict__ unary, float* __restrict__ out,
    const __half2 w1h, const __half2 w4h,
    const __half2 wa01, const __half2 wa23,
    const __half2 ws01, const __half2 ws23,
    const __half2 ccA0, const __half2 ccA1, const __half2 ccA2, const __half2 ccA3,
    const __half2 ccB0, const __half2 ccB1, const __half2 ccB2, const __half2 ccB3)
{
    constexpr int HR0 = IT, HR1 = EY - IT;
    constexpr int HC0 = 2 * IT + 2;
    constexpr int HWID = EX - 4 - 4 * IT;   // 136 / 132 / 128
    constexpr int PP   = HWID / 2;          // 68 / 66 / 64 pairs per row
    constexpr int EP   = PP - 64;           // 4 / 2 / 0 extra pairs
    constexpr int LOG2EP = (EP == 4) ? 2 : 1;
    constexpr int EXTRA = HWID - 128;       // 8 / 4 / 0 (scalar V extra cols)
    constexpr int SHV   = (EXTRA == 8) ? 3 : 2;
    constexpr int UR0 = IT + 1, UR1 = EY - 1 - IT;

    // ---- Horizontal 5-tap pass on point pairs (small live set, no spill) ----
    auto h_pair = [&](int c) {   // c even: points c, c+1
        const uint4 A = *reinterpret_cast<const uint4*>(&sQin[c - 2]);
        const uint4 B = *reinterpret_cast<const uint4*>(&sQin[c]);
        const uint4 C = *reinterpret_cast<const uint4*>(&sQin[c + 2]);
        const __half2 h00 = __hfma2(w4h, __hadd2(u2h(A.x), u2h(C.x)),
                            __hfma2(w1h, __hadd2(u2h(A.z), u2h(B.z)), u2h(B.x)));
        const __half2 h01 = __hfma2(w4h, __hadd2(u2h(A.y), u2h(C.y)),
                            __hfma2(w1h, __hadd2(u2h(A.w), u2h(B.w)), u2h(B.y)));
        const __half2 h10 = __hfma2(w4h, __hadd2(u2h(A.z), u2h(C.z)),
                            __hfma2(w1h, __hadd2(u2h(B.x), u2h(C.x)), u2h(B.z)));
        const __half2 h11 = __hfma2(w4h, __hadd2(u2h(A.w), u2h(C.w)),
                            __hfma2(w1h, __hadd2(u2h(B.y), u2h(C.y)), u2h(B.w)));
        *reinterpret_cast<uint4*>(&sH[c]) =
            make_uint4(h2u(h00), h2u(h01), h2u(h10), h2u(h11));
    };

    {
        const int px = tid & 63;
        for (int r = HR0 + (tid >> 6); r < HR1; r += NTHREADS >> 6)
            h_pair(r * EX + HC0 + 2 * px);
        if (EP > 0) {
            const int px2 = 64 + (tid & (EP - 1));
            const int r = HR0 + (tid >> LOG2EP);
            if (r < HR1) h_pair(r * EX + HC0 + 2 * px2);
        }
    }
    __syncthreads();

    // PDL: first consumption of g_alive / g_beta happens in iter-0 V-pass.
    // Delay the dependency wait on crf_setup until here so Phase 0 + iter-0
    // H-pass overlap with the setup kernel's tail.
    if (IT == 0) cudaGridDependencySynchronize();

    // ---- Vertical 3-tap + update (scalar per point, R9-proven) ----
    auto u_point = [&](int row, int col) {
        const int c  = row * EX + col;
        const int gy = ty0 + row - 3;
        const int gx = tx0 + col - 6;
        if (!LAST) {
            if (gy < 0 || gy >= Hn || gx < 0 || gx >= Wn) {
                sQout[c] = make_uint2(0u, 0u);
                return;
            }
        }
        const int g   = gy * Wn + gx;
        const int pix = b * HWn + g;
        const int gg  = b * CHWn + g;

        const unsigned char alive = g_alive[pix];

        const uint2 hm = sH[c - EX];
        const uint2 h0 = sH[c];
        const uint2 hp = sH[c + EX];
        const uint2 qc = sQin[c];

        // S = H0 + W1*(Hm+Hp) - Qc
        const __half2 s01 = __hsub2(
            __hfma2(w1h, __hadd2(u2h(hm.x), u2h(hp.x)), u2h(h0.x)), u2h(qc.x));
        const __half2 s23 = __hsub2(
            __hfma2(w1h, __hadd2(u2h(hm.y), u2h(hp.y)), u2h(h0.y)), u2h(qc.y));

        __half2 a01 = __float2half2_rn(0.f);
        __half2 a23 = a01;
        if (alive) {
            const float* __restrict__ bp = g_beta + (size_t)pix * 14;
            const int offs[14] = {
                -EX - 2, -EX - 1, -EX, -EX + 1, -EX + 2,
                      -2,      -1,           1,       2,
                 EX - 2,  EX - 1,  EX,  EX + 1,  EX + 2
            };
            #pragma unroll
            for (int t = 0; t < 14; ++t) {
                const __half2 bmh = __float2half2_rn(bp[t]);
                const uint2 q = sQin[c + offs[t]];
                a01 = __hfma2(bmh, u2h(q.x), a01);
                a23 = __hfma2(bmh, u2h(q.y), a23);
            }
        }

        const __half2 wk01 = __hmul2(s01, __hfma2(wa01, a01, ws01));
        const __half2 wk23 = __hmul2(s23, __hfma2(wa23, a23, ws23));

        __half2 pw01 = __hmul2(__low2half2(wk01), ccA0);
        pw01 = __hfma2(__high2half2(wk01), ccA1, pw01);
        pw01 = __hfma2(__low2half2(wk23),  ccA2, pw01);
        pw01 = __hfma2(__high2half2(wk23), ccA3, pw01);
        __half2 pw23 = __hmul2(__low2half2(wk01), ccB0);
        pw23 = __hfma2(__high2half2(wk01), ccB1, pw23);
        pw23 = __hfma2(__low2half2(wk23),  ccB2, pw23);
        pw23 = __hfma2(__high2half2(wk23), ccB3, pw23);

        const float2 p01 = __half22float2(pw01);
        const float2 p23 = __half22float2(pw23);

        const float r0 = unary[gg]           - p01.x;
        const float r1 = unary[gg + HWn]     - p01.y;
        const float r2 = unary[gg + 2 * HWn] - p23.x;
        const float r3 = unary[gg + 3 * HWn] - p23.y;

        if (LAST) {
            out[gg]           = r0;
            out[gg + HWn]     = r1;
            out[gg + 2 * HWn] = r2;
            out[gg + 3 * HWn] = r3;
        } else {
            const float4 sm = softmax4(make_float4(r0, r1, r2, r3));
            sQout[c] = make_uint2(h2u(__floats2half2_rn(sm.x, sm.y)),
                                  h2u(__floats2half2_rn(sm.z, sm.w)));
        }
    };

    {
        const int cx = tid & 127;
        for (int r = UR0 + (tid >> 7); r < UR1; r += NTHREADS >> 7)
            u_point(r, HC0 + cx);
        if (EXTRA > 0) {
            const int cx2 = 128 + (tid & (EXTRA - 1));
            const int r = UR0 + (tid >> SHV);
            if (r < UR1) u_point(r, HC0 + cx2);
        }
    }
    if (!LAST) __syncthreads();
}

// ============================================================================
// Fused kernel: 3 CRF iterations, Q in fp16 smem, ping-pong buffers.
// ============================================================================
__global__ __launch_bounds__(NTHREADS, 3)
void crf_fused(const float* __restrict__ unary,
               const float* __restrict__ wapp,
               const float* __restrict__ wsmo,
               const float* __restrict__ compat,
               float*       __restrict__ out)
{
    extern __shared__ uint2 smem[];
    uint2* sA = smem;
    uint2* sB = smem + NEXT;
    uint2* sH = smem + 2 * NEXT;

    const int b   = blockIdx.z;
    const int ty0 = blockIdx.y * TY;
    const int tx0 = blockIdx.x * TX;
    const int tid = threadIdx.x;

    // Uniform parameters -> packed half2 (params independent of crf_setup)
    const __half2 w1h  = __float2half2_rn(W1f);
    const __half2 w4h  = __float2half2_rn(W4f);
    const __half2 wa01 = __floats2half2_rn(wapp[0], wapp[1]);
    const __half2 wa23 = __floats2half2_rn(wapp[2], wapp[3]);
    const __half2 ws01 = __floats2half2_rn(wsmo[0], wsmo[1]);
    const __half2 ws23 = __floats2half2_rn(wsmo[2], wsmo[3]);
    const __half2 ccA0 = __floats2half2_rn(compat[0],  compat[4]);
    const __half2 ccA1 = __floats2half2_rn(compat[1],  compat[5]);
    const __half2 ccA2 = __floats2half2_rn(compat[2],  compat[6]);
    const __half2 ccA3 = __floats2half2_rn(compat[3],  compat[7]);
    const __half2 ccB0 = __floats2half2_rn(compat[8],  compat[12]);
    const __half2 ccB1 = __floats2half2_rn(compat[9],  compat[13]);
    const __half2 ccB2 = __floats2half2_rn(compat[10], compat[14]);
    const __half2 ccB3 = __floats2half2_rn(compat[11], compat[15]);

    // ---- Phase 0: softmax(unary) over the full extended tile -> sA ----
    // (unary is also independent of crf_setup -> runs under PDL overlap)
    for (int i = tid; i < NEXT; i += NTHREADS) {
        const int row = i / EX;
        const int col = i - row * EX;
        const int gy = ty0 + row - 3;
        const int gx = tx0 + col - 6;
        uint2 q = make_uint2(0u, 0u);
        if (gy >= 0 && gy < Hn && gx >= 0 && gx < Wn) {
            const int gg = b * CHWn + gy * Wn + gx;
            const float4 sm = softmax4(make_float4(unary[gg],
                                                   unary[gg + HWn],
                                                   unary[gg + 2 * HWn],
                                                   unary[gg + 3 * HWn]));
            q = make_uint2(h2u(__floats2half2_rn(sm.x, sm.y)),
                           h2u(__floats2half2_rn(sm.z, sm.w)));
        }
        sA[i] = q;
    }
    __syncthreads();

    crf_do_iter<0, false>(sA, sB, sH, b, ty0, tx0, tid, unary, out,
                          w1h, w4h, wa01, wa23, ws01, ws23,
                          ccA0, ccA1, ccA2, ccA3, ccB0, ccB1, ccB2, ccB3);
    crf_do_iter<1, false>(sB, sA, sH, b, ty0, tx0, tid, unary, out,
                          w1h, w4h, wa01, wa23, ws01, ws23,
                          ccA0, ccA1, ccA2, ccA3, ccB0, ccB1, ccB2, ccB3);
    crf_do_iter<2, true >(sA, sB, sH, b, ty0, tx0, tid, unary, out,
                          w1h, w4h, wa01, wa23, ws01, ws23,
                          ccA0, ccA1, ccA2, ccA3, ccB0, ccB1, ccB2, ccB3);
}

extern "C" void kernel_launch(void* const* d_in, const int* in_sizes, int n_in,
                              void* d_out, int out_size)
{
    const float* unary  = (const float*)d_in[0];
    const float* xyz    = (const float*)d_in[1];
    const float* mask   = (const float*)d_in[2];
    const float* wapp   = (const float*)d_in[3];
    const float* wsmo   = (const float*)d_in[4];
    const float* compat = (const float*)d_in[5];
    float* out = (float*)d_out;

    cudaFuncSetAttribute(crf_fused, cudaFuncAttributeMaxDynamicSharedMemorySize,
                         SMEM_BYTES);

    // Setup (primary)
    dim3 sgrid(Wn / TX, Hn / STY, Bn);
    crf_setup<<<sgrid, SNT>>>(xyz, mask);

    // Fused (secondary) with programmatic dependent launch: starts while setup
    // drains; waits on it only at cudaGridDependencySynchronize() in iter 0.
    dim3 grid(Wn / TX, Hn / TY, Bn);

    cudaLaunchConfig_t cfg = {};
    cfg.gridDim = grid;
    cfg.blockDim = dim3(NTHREADS);
    cfg.dynamicSmemBytes = SMEM_BYTES;
    cfg.stream = 0;   // same (legacy default) stream as crf_setup

    cudaLaunchAttribute attrs[1];
    attrs[0].id = cudaLaunchAttributeProgrammaticStreamSerialization;
    attrs[0].val.programmaticStreamSerializationAllowed = 1;
    cfg.attrs = attrs;
    cfg.numAttrs = 1;

    cudaLaunchKernelEx(&cfg, crf_fused, unary, wapp, wsmo, compat, out);
}

// round 14
// speedup vs baseline: 1.9706x; 1.0471x over previous
#include <cuda_runtime.h>
#include <cuda_fp16.h>

// Problem constants
#define Bn 8
#define Hn 64
#define Wn 2048
#define HWn (Hn * Wn)          // 131072
#define CHWn (4 * HWn)         // 524288

// Fused-kernel tile: 128x16 output, +-6 x / +-3 y halo for 3 iterations
#define TX 128
#define TY 16
#define EX 140
#define EY 22
#define NEXT (EX * EY)         // 3080
#define NTHREADS 512

// Setup-kernel tile (single-iteration halo)
#define STY 16
#define SNT 256
#define SHX (TX + 4)           // 132
#define SHY (STY + 2)          // 18
#define SHALO (SHX * SHY)      // 2376

// Separable Gaussian weights: exp(-d^2/(2*0.9^2)) for d=1,2
#define W1f 0.53940751f
#define W4f 0.08465798f

// C2 = -1/(2*0.015^2) * log2(e)
#define C2f      (-3206.0005353f)
#define NEG2C2f  (6412.0010706f)
#define L2Ef     (1.4426950408889634f)
#define MASK_BIG (1.0e9f)
#define SKIP_THR (-40.0f)

#define SMEM_BYTES (3 * NEXT * (int)sizeof(uint2))   // 73920

// Iteration-invariant appearance data (allocation forbidden -> device globals)
__device__ unsigned char g_alive[Bn * HWn];
__device__ float         g_beta[Bn * HWn * 14];

// ---- helpers ----
__device__ __forceinline__ float ex2(float x) {
    float r;
    asm("ex2.approx.ftz.f32 %0, %1;" : "=f"(r) : "f"(x));
    return r;
}
__device__ __forceinline__ __half2 u2h(unsigned u) {
    __half2 h;
    *reinterpret_cast<unsigned*>(&h) = u;
    return h;
}
__device__ __forceinline__ unsigned h2u(__half2 h) {
    return *reinterpret_cast<unsigned*>(&h);
}
// Softmax without max-subtraction: |q| <= ~8 here, far from fp32 exp2 limits.
__device__ __forceinline__ float4 softmax4(float4 q) {
    const float p0 = ex2(q.x * L2Ef);
    const float p1 = ex2(q.y * L2Ef);
    const float p2 = ex2(q.z * L2Ef);
    const float p3 = ex2(q.w * L2Ef);
    const float inv = __fdividef(1.0f, p0 + p1 + p2 + p3);
    return make_float4(p0 * inv, p1 * inv, p2 * inv, p3 * inv);
}

// ============================================================================
// Setup: per-pixel alive flag + (rare) exact beta taps. Iteration-invariant.
// ============================================================================
__global__ __launch_bounds__(SNT)
void crf_setup(const float* __restrict__ xyz,
               const float* __restrict__ mask)
{
    // PDL: allow the dependent crf_fused grid to start launching NOW.
    // Its cudaGridDependencySynchronize() still waits for our writes, but its
    // setup-independent prologue (Phase 0 softmax + iter-0 H-pass) overlaps
    // with this kernel's execution.
    cudaTriggerProgrammaticLaunchCompletion();

    __shared__ float4 sG[SHALO];

    const int b   = blockIdx.z;
    const int ty0 = blockIdx.y * STY;
    const int tx0 = blockIdx.x * TX;
    const int tid = threadIdx.x;

    const float* __restrict__ Xb = xyz  + b * 3 * HWn;
    const float* __restrict__ Mb = mask + b * HWn;

    for (int i = tid; i < SHALO; i += SNT) {
        const int hy = i / SHX;
        const int hx = i - hy * SHX;
        const int gy = ty0 + hy - 1;
        const int gx = tx0 + hx - 2;
        float4 sg = make_float4(0.f, 0.f, 0.f, -MASK_BIG);
        if (gy >= 0 && gy < Hn && gx >= 0 && gx < Wn) {
            const int g = gy * Wn + gx;
            const float x = Xb[g];
            const float y = Xb[g + HWn];
            const float z = Xb[g + 2 * HWn];
            const float m = Mb[g];
            float nrm = x * x;
            nrm = fmaf(y, y, nrm);
            nrm = fmaf(z, z, nrm);
            sg.x = x; sg.y = y; sg.z = z;
            sg.w = fmaf(nrm, C2f, fmaf(m, MASK_BIG, -MASK_BIG));
        }
        sG[i] = sg;
    }
    __syncthreads();

    const int offs[14] = {
        -SHX - 2, -SHX - 1, -SHX, -SHX + 1, -SHX + 2,
               -2,       -1,            1,        2,
         SHX - 2,  SHX - 1,  SHX,  SHX + 1,  SHX + 2
    };

    for (int k = 0; k < (TX * STY) / SNT; ++k) {
        const int p  = tid + k * SNT;
        const int ty = p >> 7;
        const int tx = p & (TX - 1);
        const int base = (ty + 1) * SHX + (tx + 2);

        const float4 ga = sG[base];
        const float axs = ga.x * NEG2C2f;
        const float ays = ga.y * NEG2C2f;
        const float azs = ga.z * NEG2C2f;
        const float na  = ga.w;

        float maxa = -MASK_BIG;
        #pragma unroll
        for (int t = 0; t < 14; ++t) {
            const float4 gn = sG[base + offs[t]];
            const float arg = fmaf(gn.x, axs,
                              fmaf(gn.y, ays,
                              fmaf(gn.z, azs, gn.w + na)));
            maxa = fmaxf(maxa, arg);
        }

        const bool alive = (maxa > SKIP_THR) && (na > -1.0e8f);
        const int pix = b * HWn + (ty0 + ty) * Wn + (tx0 + tx);
        g_alive[pix] = alive ? 1 : 0;

        if (alive) {
            #pragma unroll
            for (int t = 0; t < 14; ++t) {
                const float4 gn = sG[base + offs[t]];
                const float arg = fmaf(gn.x, axs,
                                  fmaf(gn.y, ays,
                                  fmaf(gn.z, azs, gn.w + na)));
                g_beta[pix * 14 + t] = ex2(arg);
            }
        }
    }
}

// ============================================================================
// One in-smem CRF iteration (fp16 storage, paired H-pass, scalar V-pass).
// ============================================================================
template<int IT, bool LAST>
__device__ __forceinline__ void crf_do_iter(
    const uint2* __restrict__ sQin, uint2* __restrict__ sQout,
    uint2* __restrict__ sH,
    const int b, const int ty0, const int tx0, const int tid,
    const float* __restrict__ unary, float* __restrict__ out,
    const __half2 w1h, const __half2 w4h,
    const __half2 wa01, const __half2 wa23,
    const __half2 ws01, const __half2 ws23,
    const __half2 ccA0, const __half2 ccA1, const __half2 ccA2, const __half2 ccA3,
    const __half2 ccB0, const __half2 ccB1, const __half2 ccB2, const __half2 ccB3)
{
    constexpr int HR0 = IT, HR1 = EY - IT;
    constexpr int HC0 = 2 * IT + 2;
    constexpr int HWID = EX - 4 - 4 * IT;   // 136 / 132 / 128
    constexpr int PP   = HWID / 2;          // 68 / 66 / 64 pairs per row
    constexpr int EP   = PP - 64;           // 4 / 2 / 0 extra pairs
    constexpr int LOG2EP = (EP == 4) ? 2 : 1;
    constexpr int EXTRA = HWID - 128;       // 8 / 4 / 0 (scalar V extra cols)
    constexpr int SHV   = (EXTRA == 8) ? 3 : 2;
    constexpr int UR0 = IT + 1, UR1 = EY - 1 - IT;

    // ---- Horizontal 5-tap pass on point pairs (small live set, no spill) ----
    auto h_pair = [&](int c) {   // c even: points c, c+1
        const uint4 A = *reinterpret_cast<const uint4*>(&sQin[c - 2]);
        const uint4 B = *reinterpret_cast<const uint4*>(&sQin[c]);
        const uint4 C = *reinterpret_cast<const uint4*>(&sQin[c + 2]);
        const __half2 h00 = __hfma2(w4h, __hadd2(u2h(A.x), u2h(C.x)),
                            __hfma2(w1h, __hadd2(u2h(A.z), u2h(B.z)), u2h(B.x)));
        const __half2 h01 = __hfma2(w4h, __hadd2(u2h(A.y), u2h(C.y)),
                            __hfma2(w1h, __hadd2(u2h(A.w), u2h(B.w)), u2h(B.y)));
        const __half2 h10 = __hfma2(w4h, __hadd2(u2h(A.z), u2h(C.z)),
                            __hfma2(w1h, __hadd2(u2h(B.x), u2h(C.x)), u2h(B.z)));
        const __half2 h11 = __hfma2(w4h, __hadd2(u2h(A.w), u2h(C.w)),
                            __hfma2(w1h, __hadd2(u2h(B.y), u2h(C.y)), u2h(B.w)));
        *reinterpret_cast<uint4*>(&sH[c]) =
            make_uint4(h2u(h00), h2u(h01), h2u(h10), h2u(h11));
    };

    {
        const int px = tid & 63;
        for (int r = HR0 + (tid >> 6); r < HR1; r += NTHREADS >> 6)
            h_pair(r * EX + HC0 + 2 * px);
        if (EP > 0) {
            const int px2 = 64 + (tid & (EP - 1));
            const int r = HR0 + (tid >> LOG2EP);
            if (r < HR1) h_pair(r * EX + HC0 + 2 * px2);
        }
    }
    __syncthreads();

    // PDL: first consumption of g_alive / g_beta happens in iter-0 V-pass.
    if (IT == 0) cudaGridDependencySynchronize();

    // ---- Vertical 3-tap + update (scalar per point, R9-proven) ----
    auto u_point = [&](int row, int col) {
        const int c  = row * EX + col;
        const int gy = ty0 + row - 3;
        const int gx = tx0 + col - 6;
        if (!LAST) {
            if (gy < 0 || gy >= Hn || gx < 0 || gx >= Wn) {
                sQout[c] = make_uint2(0u, 0u);
                return;
            }
        }
        const int g   = gy * Wn + gx;
        const int pix = b * HWn + g;
        const int gg  = b * CHWn + g;

        const unsigned char alive = g_alive[pix];

        const uint2 hm = sH[c - EX];
        const uint2 h0 = sH[c];
        const uint2 hp = sH[c + EX];
        const uint2 qc = sQin[c];

        // S = H0 + W1*(Hm+Hp) - Qc
        const __half2 s01 = __hsub2(
            __hfma2(w1h, __hadd2(u2h(hm.x), u2h(hp.x)), u2h(h0.x)), u2h(qc.x));
        const __half2 s23 = __hsub2(
            __hfma2(w1h, __hadd2(u2h(hm.y), u2h(hp.y)), u2h(h0.y)), u2h(qc.y));

        __half2 a01 = __float2half2_rn(0.f);
        __half2 a23 = a01;
        if (alive) {
            const float* __restrict__ bp = g_beta + (size_t)pix * 14;
            const int offs[14] = {
                -EX - 2, -EX - 1, -EX, -EX + 1, -EX + 2,
                      -2,      -1,           1,       2,
                 EX - 2,  EX - 1,  EX,  EX + 1,  EX + 2
            };
            #pragma unroll
            for (int t = 0; t < 14; ++t) {
                const __half2 bmh = __float2half2_rn(bp[t]);
                const uint2 q = sQin[c + offs[t]];
                a01 = __hfma2(bmh, u2h(q.x), a01);
                a23 = __hfma2(bmh, u2h(q.y), a23);
            }
        }

        const __half2 wk01 = __hmul2(s01, __hfma2(wa01, a01, ws01));
        const __half2 wk23 = __hmul2(s23, __hfma2(wa23, a23, ws23));

        __half2 pw01 = __hmul2(__low2half2(wk01), ccA0);
        pw01 = __hfma2(__high2half2(wk01), ccA1, pw01);
        pw01 = __hfma2(__low2half2(wk23),  ccA2, pw01);
        pw01 = __hfma2(__high2half2(wk23), ccA3, pw01);
        __half2 pw23 = __hmul2(__low2half2(wk01), ccB0);
        pw23 = __hfma2(__high2half2(wk01), ccB1, pw23);
        pw23 = __hfma2(__low2half2(wk23),  ccB2, pw23);
        pw23 = __hfma2(__high2half2(wk23), ccB3, pw23);

        const float2 p01 = __half22float2(pw01);
        const float2 p23 = __half22float2(pw23);

        const float r0 = unary[gg]           - p01.x;
        const float r1 = unary[gg + HWn]     - p01.y;
        const float r2 = unary[gg + 2 * HWn] - p23.x;
        const float r3 = unary[gg + 3 * HWn] - p23.y;

        if (LAST) {
            out[gg]           = r0;
            out[gg + HWn]     = r1;
            out[gg + 2 * HWn] = r2;
            out[gg + 3 * HWn] = r3;
        } else {
            const float4 sm = softmax4(make_float4(r0, r1, r2, r3));
            sQout[c] = make_uint2(h2u(__floats2half2_rn(sm.x, sm.y)),
                                  h2u(__floats2half2_rn(sm.z, sm.w)));
        }
    };

    {
        const int cx = tid & 127;
        for (int r = UR0 + (tid >> 7); r < UR1; r += NTHREADS >> 7)
            u_point(r, HC0 + cx);
        if (EXTRA > 0) {
            const int cx2 = 128 + (tid & (EXTRA - 1));
            const int r = UR0 + (tid >> SHV);
            if (r < UR1) u_point(r, HC0 + cx2);
        }
    }
    if (!LAST) __syncthreads();
}

// ============================================================================
// Fused kernel: 3 CRF iterations, Q in fp16 smem, ping-pong buffers.
// ============================================================================
__global__ __launch_bounds__(NTHREADS, 3)
void crf_fused(const float* __restrict__ unary,
               const float* __restrict__ wapp,
               const float* __restrict__ wsmo,
               const float* __restrict__ compat,
               float*       __restrict__ out)
{
    extern __shared__ uint2 smem[];
    uint2* sA = smem;
    uint2* sB = smem + NEXT;
    uint2* sH = smem + 2 * NEXT;

    const int b   = blockIdx.z;
    const int ty0 = blockIdx.y * TY;
    const int tx0 = blockIdx.x * TX;
    const int tid = threadIdx.x;

    // Uniform parameters -> packed half2 (independent of crf_setup)
    const __half2 w1h  = __float2half2_rn(W1f);
    const __half2 w4h  = __float2half2_rn(W4f);
    const __half2 wa01 = __floats2half2_rn(wapp[0], wapp[1]);
    const __half2 wa23 = __floats2half2_rn(wapp[2], wapp[3]);
    const __half2 ws01 = __floats2half2_rn(wsmo[0], wsmo[1]);
    const __half2 ws23 = __floats2half2_rn(wsmo[2], wsmo[3]);
    const __half2 ccA0 = __floats2half2_rn(compat[0],  compat[4]);
    const __half2 ccA1 = __floats2half2_rn(compat[1],  compat[5]);
    const __half2 ccA2 = __floats2half2_rn(compat[2],  compat[6]);
    const __half2 ccA3 = __floats2half2_rn(compat[3],  compat[7]);
    const __half2 ccB0 = __floats2half2_rn(compat[8],  compat[12]);
    const __half2 ccB1 = __floats2half2_rn(compat[9],  compat[13]);
    const __half2 ccB2 = __floats2half2_rn(compat[10], compat[14]);
    const __half2 ccB3 = __floats2half2_rn(compat[11], compat[15]);

    // ---- Phase 0: softmax(unary) over the full extended tile -> sA ----
    // (setup-independent; overlaps with crf_setup under PDL)
    for (int i = tid; i < NEXT; i += NTHREADS) {
        const int row = i / EX;
        const int col = i - row * EX;
        const int gy = ty0 + row - 3;
        const int gx = tx0 + col - 6;
        uint2 q = make_uint2(0u, 0u);
        if (gy >= 0 && gy < Hn && gx >= 0 && gx < Wn) {
            const int gg = b * CHWn + gy * Wn + gx;
            const float4 sm = softmax4(make_float4(unary[gg],
                                                   unary[gg + HWn],
                                                   unary[gg + 2 * HWn],
                                                   unary[gg + 3 * HWn]));
            q = make_uint2(h2u(__floats2half2_rn(sm.x, sm.y)),
                           h2u(__floats2half2_rn(sm.z, sm.w)));
        }
        sA[i] = q;
    }
    __syncthreads();

    crf_do_iter<0, false>(sA, sB, sH, b, ty0, tx0, tid, unary, out,
                          w1h, w4h, wa01, wa23, ws01, ws23,
                          ccA0, ccA1, ccA2, ccA3, ccB0, ccB1, ccB2, ccB3);
    crf_do_iter<1, false>(sB, sA, sH, b, ty0, tx0, tid, unary, out,
                          w1h, w4h, wa01, wa23, ws01, ws23,
                          ccA0, ccA1, ccA2, ccA3, ccB0, ccB1, ccB2, ccB3);
    crf_do_iter<2, true >(sA, sB, sH, b, ty0, tx0, tid, unary, out,
                          w1h, w4h, wa01, wa23, ws01, ws23,
                          ccA0, ccA1, ccA2, ccA3, ccB0, ccB1, ccB2, ccB3);
}

extern "C" void kernel_launch(void* const* d_in, const int* in_sizes, int n_in,
                              void* d_out, int out_size)
{
    const float* unary  = (const float*)d_in[0];
    const float* xyz    = (const float*)d_in[1];
    const float* mask   = (const float*)d_in[2];
    const float* wapp   = (const float*)d_in[3];
    const float* wsmo   = (const float*)d_in[4];
    const float* compat = (const float*)d_in[5];
    float* out = (float*)d_out;

    cudaFuncSetAttribute(crf_fused, cudaFuncAttributeMaxDynamicSharedMemorySize,
                         SMEM_BYTES);

    // Setup (primary) — triggers programmatic completion at block entry.
    dim3 sgrid(Wn / TX, Hn / STY, Bn);
    crf_setup<<<sgrid, SNT>>>(xyz, mask);

    // Fused (secondary) with programmatic dependent launch.
    dim3 grid(Wn / TX, Hn / TY, Bn);

    cudaLaunchConfig_t cfg = {};
    cfg.gridDim = grid;
    cfg.blockDim = dim3(NTHREADS);
    cfg.dynamicSmemBytes = SMEM_BYTES;
    cfg.stream = 0;   // same (legacy default) stream as crf_setup

    cudaLaunchAttribute attrs[1];
    attrs[0].id = cudaLaunchAttributeProgrammaticStreamSerialization;
    attrs[0].val.programmaticStreamSerializationAllowed = 1;
    cfg.attrs = attrs;
    cfg.numAttrs = 1;

    cudaLaunchKernelEx(&cfg, crf_fused, unary, wapp, wsmo, compat, out);
}

// round 15
// speedup vs baseline: 2.1424x; 1.0872x over previous
#include <cuda_runtime.h>
#include <cuda_fp16.h>

// Problem constants
#define Bn 8
#define Hn 64
#define Wn 2048
#define HWn (Hn * Wn)          // 131072
#define CHWn (4 * HWn)         // 524288

// Fused-kernel tile: 128x16 output, +-6 x / +-3 y halo for 3 iterations
#define TX 128
#define TY 16
#define EX 140
#define EY 22
#define NEXT (EX * EY)         // 3080
#define NTHREADS 256           // 4 blocks/SM -> single wave (512 <= 592 slots)

// Setup-kernel tile (single-iteration halo)
#define STY 16
#define SNT 256
#define SHX (TX + 4)           // 132
#define SHY (STY + 2)          // 18
#define SHALO (SHX * SHY)      // 2376

// Separable Gaussian weights: exp(-d^2/(2*0.9^2)) for d=1,2
#define W1f 0.53940751f
#define W4f 0.08465798f

// C2 = -1/(2*0.015^2) * log2(e)
#define C2f      (-3206.0005353f)
#define NEG2C2f  (6412.0010706f)
#define L2Ef     (1.4426950408889634f)
#define MASK_BIG (1.0e9f)
#define SKIP_THR (-40.0f)

// 2 smem buffers only (sQ in-place updated via register staging)
#define SMEM_BYTES (2 * NEXT * (int)sizeof(uint2))   // 49280 <= 57KB -> 4 blocks/SM

// Iteration-invariant appearance data (allocation forbidden -> device globals)
__device__ unsigned char g_alive[Bn * HWn];
__device__ float         g_beta[Bn * HWn * 14];

// ---- helpers ----
__device__ __forceinline__ float ex2(float x) {
    float r;
    asm("ex2.approx.ftz.f32 %0, %1;" : "=f"(r) : "f"(x));
    return r;
}
__device__ __forceinline__ __half2 u2h(unsigned u) {
    __half2 h;
    *reinterpret_cast<unsigned*>(&h) = u;
    return h;
}
__device__ __forceinline__ unsigned h2u(__half2 h) {
    return *reinterpret_cast<unsigned*>(&h);
}
// Softmax without max-subtraction: |q| <= ~8 here, far from fp32 exp2 limits.
__device__ __forceinline__ float4 softmax4(float4 q) {
    const float p0 = ex2(q.x * L2Ef);
    const float p1 = ex2(q.y * L2Ef);
    const float p2 = ex2(q.z * L2Ef);
    const float p3 = ex2(q.w * L2Ef);
    const float inv = __fdividef(1.0f, p0 + p1 + p2 + p3);
    return make_float4(p0 * inv, p1 * inv, p2 * inv, p3 * inv);
}

// ============================================================================
// Setup: per-pixel alive flag + (rare) exact beta taps. Iteration-invariant.
// ============================================================================
__global__ __launch_bounds__(SNT)
void crf_setup(const float* __restrict__ xyz,
               const float* __restrict__ mask)
{
    // PDL: allow dependent crf_fused to start its setup-independent prologue.
    cudaTriggerProgrammaticLaunchCompletion();

    __shared__ float4 sG[SHALO];

    const int b   = blockIdx.z;
    const int ty0 = blockIdx.y * STY;
    const int tx0 = blockIdx.x * TX;
    const int tid = threadIdx.x;

    const float* __restrict__ Xb = xyz  + b * 3 * HWn;
    const float* __restrict__ Mb = mask + b * HWn;

    for (int i = tid; i < SHALO; i += SNT) {
        const int hy = i / SHX;
        const int hx = i - hy * SHX;
        const int gy = ty0 + hy - 1;
        const int gx = tx0 + hx - 2;
        float4 sg = make_float4(0.f, 0.f, 0.f, -MASK_BIG);
        if (gy >= 0 && gy < Hn && gx >= 0 && gx < Wn) {
            const int g = gy * Wn + gx;
            const float x = Xb[g];
            const float y = Xb[g + HWn];
            const float z = Xb[g + 2 * HWn];
            const float m = Mb[g];
            float nrm = x * x;
            nrm = fmaf(y, y, nrm);
            nrm = fmaf(z, z, nrm);
            sg.x = x; sg.y = y; sg.z = z;
            sg.w = fmaf(nrm, C2f, fmaf(m, MASK_BIG, -MASK_BIG));
        }
        sG[i] = sg;
    }
    __syncthreads();

    const int offs[14] = {
        -SHX - 2, -SHX - 1, -SHX, -SHX + 1, -SHX + 2,
               -2,       -1,            1,        2,
         SHX - 2,  SHX - 1,  SHX,  SHX + 1,  SHX + 2
    };

    for (int k = 0; k < (TX * STY) / SNT; ++k) {
        const int p  = tid + k * SNT;
        const int ty = p >> 7;
        const int tx = p & (TX - 1);
        const int base = (ty + 1) * SHX + (tx + 2);

        const float4 ga = sG[base];
        const float axs = ga.x * NEG2C2f;
        const float ays = ga.y * NEG2C2f;
        const float azs = ga.z * NEG2C2f;
        const float na  = ga.w;

        float maxa = -MASK_BIG;
        #pragma unroll
        for (int t = 0; t < 14; ++t) {
            const float4 gn = sG[base + offs[t]];
            const float arg = fmaf(gn.x, axs,
                              fmaf(gn.y, ays,
                              fmaf(gn.z, azs, gn.w + na)));
            maxa = fmaxf(maxa, arg);
        }

        const bool alive = (maxa > SKIP_THR) && (na > -1.0e8f);
        const int pix = b * HWn + (ty0 + ty) * Wn + (tx0 + tx);
        g_alive[pix] = alive ? 1 : 0;

        if (alive) {
            #pragma unroll
            for (int t = 0; t < 14; ++t) {
                const float4 gn = sG[base + offs[t]];
                const float arg = fmaf(gn.x, axs,
                                  fmaf(gn.y, ays,
                                  fmaf(gn.z, azs, gn.w + na)));
                g_beta[pix * 14 + t] = ex2(arg);
            }
        }
    }
}

// ============================================================================
// One in-smem CRF iteration. H-pass paired into sH; V-pass computes newQ,
// stages it packed-fp16 in registers, then writes IN PLACE into sQ.
// ============================================================================
template<int IT, bool LAST>
__device__ __forceinline__ void crf_do_iter(
    uint2* __restrict__ sQ, uint2* __restrict__ sH,
    const int b, const int ty0, const int tx0, const int tid,
    const float* __restrict__ unary, float* __restrict__ out,
    const __half2 w1h, const __half2 w4h,
    const __half2 wa01, const __half2 wa23,
    const __half2 ws01, const __half2 ws23,
    const __half2 ccA0, const __half2 ccA1, const __half2 ccA2, const __half2 ccA3,
    const __half2 ccB0, const __half2 ccB1, const __half2 ccB2, const __half2 ccB3)
{
    constexpr int HR0 = IT, HR1 = EY - IT;
    constexpr int HC0 = 2 * IT + 2;
    constexpr int HWID = EX - 4 - 4 * IT;   // 136 / 132 / 128
    constexpr int PP   = HWID / 2;          // 68 / 66 / 64 pairs per row
    constexpr int EP   = PP - 64;           // 4 / 2 / 0 extra pairs
    constexpr int LOG2EP = (EP == 4) ? 2 : 1;
    constexpr int EXTRA = HWID - 128;       // 8 / 4 / 0 (scalar V extra cols)
    constexpr int SHV   = (EXTRA == 8) ? 3 : 2;
    constexpr int UR0 = IT + 1, UR1 = EY - 1 - IT;
    constexpr int UROWS = UR1 - UR0;        // 20 / 18 / 16 (even)
    constexpr int RSTRIDE = NTHREADS >> 7;  // 2 rows covered per sweep
    constexpr int NMAIN = UROWS / RSTRIDE;  // 10 / 9 / 8 main points per thread

    // ---- Horizontal 5-tap pass on point pairs ----
    auto h_pair = [&](int c) {   // c even: points c, c+1
        const uint4 A = *reinterpret_cast<const uint4*>(&sQ[c - 2]);
        const uint4 B = *reinterpret_cast<const uint4*>(&sQ[c]);
        const uint4 C = *reinterpret_cast<const uint4*>(&sQ[c + 2]);
        const __half2 h00 = __hfma2(w4h, __hadd2(u2h(A.x), u2h(C.x)),
                            __hfma2(w1h, __hadd2(u2h(A.z), u2h(B.z)), u2h(B.x)));
        const __half2 h01 = __hfma2(w4h, __hadd2(u2h(A.y), u2h(C.y)),
                            __hfma2(w1h, __hadd2(u2h(A.w), u2h(B.w)), u2h(B.y)));
        const __half2 h10 = __hfma2(w4h, __hadd2(u2h(A.z), u2h(C.z)),
                            __hfma2(w1h, __hadd2(u2h(B.x), u2h(C.x)), u2h(B.z)));
        const __half2 h11 = __hfma2(w4h, __hadd2(u2h(A.w), u2h(C.w)),
                            __hfma2(w1h, __hadd2(u2h(B.y), u2h(C.y)), u2h(B.w)));
        *reinterpret_cast<uint4*>(&sH[c]) =
            make_uint4(h2u(h00), h2u(h01), h2u(h10), h2u(h11));
    };

    {
        const int px = tid & 63;
        for (int r = HR0 + (tid >> 6); r < HR1; r += NTHREADS >> 6)
            h_pair(r * EX + HC0 + 2 * px);
        if (EP > 0) {
            const int px2 = 64 + (tid & (EP - 1));
            for (int r = HR0 + (tid >> LOG2EP); r < HR1; r += NTHREADS >> LOG2EP)
                h_pair(r * EX + HC0 + 2 * px2);
        }
    }
    __syncthreads();

    // PDL: first consumption of g_alive / g_beta happens in iter-0 V-pass.
    if (IT == 0) cudaGridDependencySynchronize();

    // ---- Vertical 3-tap + update; returns packed newQ (or writes out) ----
    auto u_point = [&](int row, int col) -> uint2 {
        const int c  = row * EX + col;
        const int gy = ty0 + row - 3;
        const int gx = tx0 + col - 6;
        if (!LAST) {
            if (gy < 0 || gy >= Hn || gx < 0 || gx >= Wn)
                return make_uint2(0u, 0u);
        }
        const int g   = gy * Wn + gx;
        const int pix = b * HWn + g;
        const int gg  = b * CHWn + g;

        const unsigned char alive = g_alive[pix];

        const uint2 hm = sH[c - EX];
        const uint2 h0 = sH[c];
        const uint2 hp = sH[c + EX];
        const uint2 qc = sQ[c];

        // S = H0 + W1*(Hm+Hp) - Qc
        const __half2 s01 = __hsub2(
            __hfma2(w1h, __hadd2(u2h(hm.x), u2h(hp.x)), u2h(h0.x)), u2h(qc.x));
        const __half2 s23 = __hsub2(
            __hfma2(w1h, __hadd2(u2h(hm.y), u2h(hp.y)), u2h(h0.y)), u2h(qc.y));

        __half2 a01 = __float2half2_rn(0.f);
        __half2 a23 = a01;
        if (alive) {
            const float* __restrict__ bp = g_beta + (size_t)pix * 14;
            const int offs[14] = {
                -EX - 2, -EX - 1, -EX, -EX + 1, -EX + 2,
                      -2,      -1,           1,       2,
                 EX - 2,  EX - 1,  EX,  EX + 1,  EX + 2
            };
            #pragma unroll
            for (int t = 0; t < 14; ++t) {
                const __half2 bmh = __float2half2_rn(bp[t]);
                const uint2 q = sQ[c + offs[t]];
                a01 = __hfma2(bmh, u2h(q.x), a01);
                a23 = __hfma2(bmh, u2h(q.y), a23);
            }
        }

        const __half2 wk01 = __hmul2(s01, __hfma2(wa01, a01, ws01));
        const __half2 wk23 = __hmul2(s23, __hfma2(wa23, a23, ws23));

        __half2 pw01 = __hmul2(__low2half2(wk01), ccA0);
        pw01 = __hfma2(__high2half2(wk01), ccA1, pw01);
        pw01 = __hfma2(__low2half2(wk23),  ccA2, pw01);
        pw01 = __hfma2(__high2half2(wk23), ccA3, pw01);
        __half2 pw23 = __hmul2(__low2half2(wk01), ccB0);
        pw23 = __hfma2(__high2half2(wk01), ccB1, pw23);
        pw23 = __hfma2(__low2half2(wk23),  ccB2, pw23);
        pw23 = __hfma2(__high2half2(wk23), ccB3, pw23);

        const float2 p01 = __half22float2(pw01);
        const float2 p23 = __half22float2(pw23);

        const float r0 = unary[gg]           - p01.x;
        const float r1 = unary[gg + HWn]     - p01.y;
        const float r2 = unary[gg + 2 * HWn] - p23.x;
        const float r3 = unary[gg + 3 * HWn] - p23.y;

        if (LAST) {
            out[gg]           = r0;
            out[gg + HWn]     = r1;
            out[gg + 2 * HWn] = r2;
            out[gg + 3 * HWn] = r3;
            return make_uint2(0u, 0u);
        } else {
            const float4 sm = softmax4(make_float4(r0, r1, r2, r3));
            return make_uint2(h2u(__floats2half2_rn(sm.x, sm.y)),
                              h2u(__floats2half2_rn(sm.z, sm.w)));
        }
    };

    const int cx   = tid & 127;            // main column within [HC0, HC0+128)
    const int rb   = tid >> 7;             // 0..1: row phase
    const int cxE  = 128 + (tid & (EXTRA > 0 ? (EXTRA - 1) : 0));
    const int rE   = UR0 + (tid >> SHV);   // extra-col row (EXTRA>0)

    if (LAST) {
        // Direct global writes; no staging needed.
        for (int k = 0; k < NMAIN; ++k)
            (void)u_point(UR0 + rb + k * RSTRIDE, HC0 + cx);
        if (EXTRA > 0 && rE < UR1)
            (void)u_point(rE, HC0 + cxE);
    } else {
        // Stage packed-fp16 newQ in registers, then write in place into sQ.
        uint2 nq[NMAIN];
        #pragma unroll
        for (int k = 0; k < NMAIN; ++k)
            nq[k] = u_point(UR0 + rb + k * RSTRIDE, HC0 + cx);
        uint2 nqE = make_uint2(0u, 0u);
        const bool doE = (EXTRA > 0) && (rE < UR1);
        if (doE) nqE = u_point(rE, HC0 + cxE);

        __syncthreads();   // everyone done READING sQ/sH

        #pragma unroll
        for (int k = 0; k < NMAIN; ++k)
            sQ[(UR0 + rb + k * RSTRIDE) * EX + HC0 + cx] = nq[k];
        if (doE)
            sQ[rE * EX + HC0 + cxE] = nqE;

        __syncthreads();   // writes visible before next iteration reads
    }
}

// ============================================================================
// Fused kernel: 3 CRF iterations, single fp16 Q buffer + H scratch in smem.
// ============================================================================
__global__ __launch_bounds__(NTHREADS, 4)
void crf_fused(const float* __restrict__ unary,
               const float* __restrict__ wapp,
               const float* __restrict__ wsmo,
               const float* __restrict__ compat,
               float*       __restrict__ out)
{
    extern __shared__ uint2 smem[];
    uint2* sQ = smem;
    uint2* sH = smem + NEXT;

    const int b   = blockIdx.z;
    const int ty0 = blockIdx.y * TY;
    const int tx0 = blockIdx.x * TX;
    const int tid = threadIdx.x;

    // Uniform parameters -> packed half2 (independent of crf_setup)
    const __half2 w1h  = __float2half2_rn(W1f);
    const __half2 w4h  = __float2half2_rn(W4f);
    const __half2 wa01 = __floats2half2_rn(wapp[0], wapp[1]);
    const __half2 wa23 = __floats2half2_rn(wapp[2], wapp[3]);
    const __half2 ws01 = __floats2half2_rn(wsmo[0], wsmo[1]);
    const __half2 ws23 = __floats2half2_rn(wsmo[2], wsmo[3]);
    const __half2 ccA0 = __floats2half2_rn(compat[0],  compat[4]);
    const __half2 ccA1 = __floats2half2_rn(compat[1],  compat[5]);
    const __half2 ccA2 = __floats2half2_rn(compat[2],  compat[6]);
    const __half2 ccA3 = __floats2half2_rn(compat[3],  compat[7]);
    const __half2 ccB0 = __floats2half2_rn(compat[8],  compat[12]);
    const __half2 ccB1 = __floats2half2_rn(compat[9],  compat[13]);
    const __half2 ccB2 = __floats2half2_rn(compat[10], compat[14]);
    const __half2 ccB3 = __floats2half2_rn(compat[11], compat[15]);

    // ---- Phase 0: softmax(unary) over the full extended tile -> sQ ----
    // (setup-independent; overlaps with crf_setup under PDL)
    for (int i = tid; i < NEXT; i += NTHREADS) {
        const int row = i / EX;
        const int col = i - row * EX;
        const int gy = ty0 + row - 3;
        const int gx = tx0 + col - 6;
        uint2 q = make_uint2(0u, 0u);
        if (gy >= 0 && gy < Hn && gx >= 0 && gx < Wn) {
            const int gg = b * CHWn + gy * Wn + gx;
            const float4 sm = softmax4(make_float4(unary[gg],
                                                   unary[gg + HWn],
                                                   unary[gg + 2 * HWn],
                                                   unary[gg + 3 * HWn]));
            q = make_uint2(h2u(__floats2half2_rn(sm.x, sm.y)),
                           h2u(__floats2half2_rn(sm.z, sm.w)));
        }
        sQ[i] = q;
    }
    __syncthreads();

    crf_do_iter<0, false>(sQ, sH, b, ty0, tx0, tid, unary, out,
                          w1h, w4h, wa01, wa23, ws01, ws23,
                          ccA0, ccA1, ccA2, ccA3, ccB0, ccB1, ccB2, ccB3);
    crf_do_iter<1, false>(sQ, sH, b, ty0, tx0, tid, unary, out,
                          w1h, w4h, wa01, wa23, ws01, ws23,
                          ccA0, ccA1, ccA2, ccA3, ccB0, ccB1, ccB2, ccB3);
    crf_do_iter<2, true >(sQ, sH, b, ty0, tx0, tid, unary, out,
                          w1h, w4h, wa01, wa23, ws01, ws23,
                          ccA0, ccA1, ccA2, ccA3, ccB0, ccB1, ccB2, ccB3);
}

extern "C" void kernel_launch(void* const* d_in, const int* in_sizes, int n_in,
                              void* d_out, int out_size)
{
    const float* unary  = (const float*)d_in[0];
    const float* xyz    = (const float*)d_in[1];
    const float* mask   = (const float*)d_in[2];
    const float* wapp   = (const float*)d_in[3];
    const float* wsmo   = (const float*)d_in[4];
    const float* compat = (const float*)d_in[5];
    float* out = (float*)d_out;

    cudaFuncSetAttribute(crf_fused, cudaFuncAttributeMaxDynamicSharedMemorySize,
                         SMEM_BYTES);

    // Setup (primary) — triggers programmatic completion at block entry.
    dim3 sgrid(Wn / TX, Hn / STY, Bn);
    crf_setup<<<sgrid, SNT>>>(xyz, mask);

    // Fused (secondary) with programmatic dependent launch.
    dim3 grid(Wn / TX, Hn / TY, Bn);

    cudaLaunchConfig_t cfg = {};
    cfg.gridDim = grid;
    cfg.blockDim = dim3(NTHREADS);
    cfg.dynamicSmemBytes = SMEM_BYTES;
    cfg.stream = 0;   // same (legacy default) stream as crf_setup

    cudaLaunchAttribute attrs[1];
    attrs[0].id = cudaLaunchAttributeProgrammaticStreamSerialization;
    attrs[0].val.programmaticStreamSerializationAllowed = 1;
    cfg.attrs = attrs;
    cfg.numAttrs = 1;

    cudaLaunchKernelEx(&cfg, crf_fused, unary, wapp, wsmo, compat, out);
}

// round 16
// speedup vs baseline: 2.1969x; 1.0254x over previous
#include <cuda_runtime.h>
#include <cuda_fp16.h>

// Problem constants
#define Bn 8
#define Hn 64
#define Wn 2048
#define HWn (Hn * Wn)          // 131072
#define CHWn (4 * HWn)         // 524288

// Fused-kernel tile: 128x32 output, +-6 x / +-3 y halo for 3 iterations
#define TX 128
#define TY 32
#define EX 140
#define EY 38
#define NEXT (EX * EY)         // 5320
#define NTHREADS 512           // 2 blocks/SM, RF-exact, single wave (256<=296)

// Setup-kernel tile (single-iteration halo)
#define STY 16
#define SNT 256
#define SHX (TX + 4)           // 132
#define SHY (STY + 2)          // 18
#define SHALO (SHX * SHY)      // 2376

// Separable Gaussian weights: exp(-d^2/(2*0.9^2)) for d=1,2
#define W1f 0.53940751f
#define W4f 0.08465798f

// C2 = -1/(2*0.015^2) * log2(e)
#define C2f      (-3206.0005353f)
#define NEG2C2f  (6412.0010706f)
#define L2Ef     (1.4426950408889634f)
#define MASK_BIG (1.0e9f)
#define SKIP_THR (-40.0f)

// 2 smem buffers (sQ in-place updated via register staging)
#define SMEM_BYTES (2 * NEXT * (int)sizeof(uint2))   // 85120 -> 2 blocks/SM

// Iteration-invariant appearance data (allocation forbidden -> device globals)
__device__ unsigned char g_alive[Bn * HWn];
__device__ float         g_beta[Bn * HWn * 14];

// ---- helpers ----
__device__ __forceinline__ float ex2(float x) {
    float r;
    asm("ex2.approx.ftz.f32 %0, %1;" : "=f"(r) : "f"(x));
    return r;
}
__device__ __forceinline__ __half2 u2h(unsigned u) {
    __half2 h;
    *reinterpret_cast<unsigned*>(&h) = u;
    return h;
}
__device__ __forceinline__ unsigned h2u(__half2 h) {
    return *reinterpret_cast<unsigned*>(&h);
}
// Softmax without max-subtraction: |q| <= ~8 here, far from fp32 exp2 limits.
__device__ __forceinline__ float4 softmax4(float4 q) {
    const float p0 = ex2(q.x * L2Ef);
    const float p1 = ex2(q.y * L2Ef);
    const float p2 = ex2(q.z * L2Ef);
    const float p3 = ex2(q.w * L2Ef);
    const float inv = __fdividef(1.0f, p0 + p1 + p2 + p3);
    return make_float4(p0 * inv, p1 * inv, p2 * inv, p3 * inv);
}

// ============================================================================
// Setup: per-pixel alive flag + (rare) exact beta taps. Iteration-invariant.
// ============================================================================
__global__ __launch_bounds__(SNT)
void crf_setup(const float* __restrict__ xyz,
               const float* __restrict__ mask)
{
    // PDL: allow dependent crf_fused to start its setup-independent prologue.
    cudaTriggerProgrammaticLaunchCompletion();

    __shared__ float4 sG[SHALO];

    const int b   = blockIdx.z;
    const int ty0 = blockIdx.y * STY;
    const int tx0 = blockIdx.x * TX;
    const int tid = threadIdx.x;

    const float* __restrict__ Xb = xyz  + b * 3 * HWn;
    const float* __restrict__ Mb = mask + b * HWn;

    for (int i = tid; i < SHALO; i += SNT) {
        const int hy = i / SHX;
        const int hx = i - hy * SHX;
        const int gy = ty0 + hy - 1;
        const int gx = tx0 + hx - 2;
        float4 sg = make_float4(0.f, 0.f, 0.f, -MASK_BIG);
        if (gy >= 0 && gy < Hn && gx >= 0 && gx < Wn) {
            const int g = gy * Wn + gx;
            const float x = Xb[g];
            const float y = Xb[g + HWn];
            const float z = Xb[g + 2 * HWn];
            const float m = Mb[g];
            float nrm = x * x;
            nrm = fmaf(y, y, nrm);
            nrm = fmaf(z, z, nrm);
            sg.x = x; sg.y = y; sg.z = z;
            sg.w = fmaf(nrm, C2f, fmaf(m, MASK_BIG, -MASK_BIG));
        }
        sG[i] = sg;
    }
    __syncthreads();

    const int offs[14] = {
        -SHX - 2, -SHX - 1, -SHX, -SHX + 1, -SHX + 2,
               -2,       -1,            1,        2,
         SHX - 2,  SHX - 1,  SHX,  SHX + 1,  SHX + 2
    };

    for (int k = 0; k < (TX * STY) / SNT; ++k) {
        const int p  = tid + k * SNT;
        const int ty = p >> 7;
        const int tx = p & (TX - 1);
        const int base = (ty + 1) * SHX + (tx + 2);

        const float4 ga = sG[base];
        const float axs = ga.x * NEG2C2f;
        const float ays = ga.y * NEG2C2f;
        const float azs = ga.z * NEG2C2f;
        const float na  = ga.w;

        float maxa = -MASK_BIG;
        #pragma unroll
        for (int t = 0; t < 14; ++t) {
            const float4 gn = sG[base + offs[t]];
            const float arg = fmaf(gn.x, axs,
                              fmaf(gn.y, ays,
                              fmaf(gn.z, azs, gn.w + na)));
            maxa = fmaxf(maxa, arg);
        }

        const bool alive = (maxa > SKIP_THR) && (na > -1.0e8f);
        const int pix = b * HWn + (ty0 + ty) * Wn + (tx0 + tx);
        g_alive[pix] = alive ? 1 : 0;

        if (alive) {
            #pragma unroll
            for (int t = 0; t < 14; ++t) {
                const float4 gn = sG[base + offs[t]];
                const float arg = fmaf(gn.x, axs,
                                  fmaf(gn.y, ays,
                                  fmaf(gn.z, azs, gn.w + na)));
                g_beta[pix * 14 + t] = ex2(arg);
            }
        }
    }
}

// ============================================================================
// One in-smem CRF iteration. H-pass paired into sH; V-pass computes newQ,
// stages it packed-fp16 in registers, then writes IN PLACE into sQ.
// ============================================================================
template<int IT, bool LAST>
__device__ __forceinline__ void crf_do_iter(
    uint2* __restrict__ sQ, uint2* __restrict__ sH,
    const int b, const int ty0, const int tx0, const int tid,
    const float* __restrict__ unary, float* __restrict__ out,
    const __half2 w1h, const __half2 w4h,
    const __half2 wa01, const __half2 wa23,
    const __half2 ws01, const __half2 ws23,
    const __half2 ccA0, const __half2 ccA1, const __half2 ccA2, const __half2 ccA3,
    const __half2 ccB0, const __half2 ccB1, const __half2 ccB2, const __half2 ccB3)
{
    constexpr int HR0 = IT, HR1 = EY - IT;
    constexpr int HC0 = 2 * IT + 2;
    constexpr int HWID = EX - 4 - 4 * IT;   // 136 / 132 / 128
    constexpr int EP   = HWID / 2 - 64;     // 4 / 2 / 0 extra pairs per row
    constexpr int LOG2EP = (EP == 4) ? 2 : 1;
    constexpr int EXTRA = HWID - 128;       // 8 / 4 / 0 (scalar V extra cols)
    constexpr int SHV   = (EXTRA == 8) ? 3 : 2;
    constexpr int UR0 = IT + 1, UR1 = EY - 1 - IT;
    constexpr int UROWS = UR1 - UR0;        // 36 / 34 / 32
    constexpr int RSTRIDE = NTHREADS >> 7;  // 4 rows covered per sweep
    constexpr int NMAIN = (UROWS + RSTRIDE - 1) / RSTRIDE;  // 9 / 9 / 8

    // ---- Horizontal 5-tap pass on point pairs ----
    auto h_pair = [&](int c) {   // c even: points c, c+1
        const uint4 A = *reinterpret_cast<const uint4*>(&sQ[c - 2]);
        const uint4 B = *reinterpret_cast<const uint4*>(&sQ[c]);
        const uint4 C = *reinterpret_cast<const uint4*>(&sQ[c + 2]);
        const __half2 h00 = __hfma2(w4h, __hadd2(u2h(A.x), u2h(C.x)),
                            __hfma2(w1h, __hadd2(u2h(A.z), u2h(B.z)), u2h(B.x)));
        const __half2 h01 = __hfma2(w4h, __hadd2(u2h(A.y), u2h(C.y)),
                            __hfma2(w1h, __hadd2(u2h(A.w), u2h(B.w)), u2h(B.y)));
        const __half2 h10 = __hfma2(w4h, __hadd2(u2h(A.z), u2h(C.z)),
                            __hfma2(w1h, __hadd2(u2h(B.x), u2h(C.x)), u2h(B.z)));
        const __half2 h11 = __hfma2(w4h, __hadd2(u2h(A.w), u2h(C.w)),
                            __hfma2(w1h, __hadd2(u2h(B.y), u2h(C.y)), u2h(B.w)));
        *reinterpret_cast<uint4*>(&sH[c]) =
            make_uint4(h2u(h00), h2u(h01), h2u(h10), h2u(h11));
    };

    {
        const int px = tid & 63;
        for (int r = HR0 + (tid >> 6); r < HR1; r += NTHREADS >> 6)
            h_pair(r * EX + HC0 + 2 * px);
        if (EP > 0) {
            const int px2 = 64 + (tid & (EP - 1));
            for (int r = HR0 + (tid >> LOG2EP); r < HR1; r += NTHREADS >> LOG2EP)
                h_pair(r * EX + HC0 + 2 * px2);
        }
    }
    __syncthreads();

    // PDL: first consumption of g_alive / g_beta happens in iter-0 V-pass.
    if (IT == 0) cudaGridDependencySynchronize();

    // ---- Vertical 3-tap + update; returns packed newQ (or writes out) ----
    auto u_point = [&](int row, int col) -> uint2 {
        const int c  = row * EX + col;
        const int gy = ty0 + row - 3;
        const int gx = tx0 + col - 6;
        if (!LAST) {
            if (gy < 0 || gy >= Hn || gx < 0 || gx >= Wn)
                return make_uint2(0u, 0u);
        }
        const int g   = gy * Wn + gx;
        const int pix = b * HWn + g;
        const int gg  = b * CHWn + g;

        const unsigned char alive = g_alive[pix];

        const uint2 hm = sH[c - EX];
        const uint2 h0 = sH[c];
        const uint2 hp = sH[c + EX];
        const uint2 qc = sQ[c];

        // S = H0 + W1*(Hm+Hp) - Qc
        const __half2 s01 = __hsub2(
            __hfma2(w1h, __hadd2(u2h(hm.x), u2h(hp.x)), u2h(h0.x)), u2h(qc.x));
        const __half2 s23 = __hsub2(
            __hfma2(w1h, __hadd2(u2h(hm.y), u2h(hp.y)), u2h(h0.y)), u2h(qc.y));

        __half2 a01 = __float2half2_rn(0.f);
        __half2 a23 = a01;
        if (alive) {
            const float* __restrict__ bp = g_beta + (size_t)pix * 14;
            const int offs[14] = {
                -EX - 2, -EX - 1, -EX, -EX + 1, -EX + 2,
                      -2,      -1,           1,       2,
                 EX - 2,  EX - 1,  EX,  EX + 1,  EX + 2
            };
            #pragma unroll
            for (int t = 0; t < 14; ++t) {
                const __half2 bmh = __float2half2_rn(bp[t]);
                const uint2 q = sQ[c + offs[t]];
                a01 = __hfma2(bmh, u2h(q.x), a01);
                a23 = __hfma2(bmh, u2h(q.y), a23);
            }
        }

        const __half2 wk01 = __hmul2(s01, __hfma2(wa01, a01, ws01));
        const __half2 wk23 = __hmul2(s23, __hfma2(wa23, a23, ws23));

        __half2 pw01 = __hmul2(__low2half2(wk01), ccA0);
        pw01 = __hfma2(__high2half2(wk01), ccA1, pw01);
        pw01 = __hfma2(__low2half2(wk23),  ccA2, pw01);
        pw01 = __hfma2(__high2half2(wk23), ccA3, pw01);
        __half2 pw23 = __hmul2(__low2half2(wk01), ccB0);
        pw23 = __hfma2(__high2half2(wk01), ccB1, pw23);
        pw23 = __hfma2(__low2half2(wk23),  ccB2, pw23);
        pw23 = __hfma2(__high2half2(wk23), ccB3, pw23);

        const float2 p01 = __half22float2(pw01);
        const float2 p23 = __half22float2(pw23);

        const float r0 = unary[gg]           - p01.x;
        const float r1 = unary[gg + HWn]     - p01.y;
        const float r2 = unary[gg + 2 * HWn] - p23.x;
        const float r3 = unary[gg + 3 * HWn] - p23.y;

        if (LAST) {
            out[gg]           = r0;
            out[gg + HWn]     = r1;
            out[gg + 2 * HWn] = r2;
            out[gg + 3 * HWn] = r3;
            return make_uint2(0u, 0u);
        } else {
            const float4 sm = softmax4(make_float4(r0, r1, r2, r3));
            return make_uint2(h2u(__floats2half2_rn(sm.x, sm.y)),
                              h2u(__floats2half2_rn(sm.z, sm.w)));
        }
    };

    const int cx   = tid & 127;            // main column within [HC0, HC0+128)
    const int rb   = tid >> 7;             // 0..3: row phase
    const int cxE  = 128 + (tid & (EXTRA > 0 ? (EXTRA - 1) : 0));
    const int rE0  = UR0 + (tid >> SHV);   // extra-col first row (EXTRA>0)
    constexpr int RSE = NTHREADS >> SHV;   // extra-col row stride

    if (LAST) {
        // Direct global writes; no staging needed.
        #pragma unroll
        for (int k = 0; k < NMAIN; ++k) {
            const int r = UR0 + rb + k * RSTRIDE;
            if (r < UR1) (void)u_point(r, HC0 + cx);
        }
        if (EXTRA > 0)
            for (int r = rE0; r < UR1; r += RSE)
                (void)u_point(r, HC0 + cxE);
    } else {
        // Stage packed-fp16 newQ in registers, then write in place into sQ.
        uint2 nq[NMAIN];
        #pragma unroll
        for (int k = 0; k < NMAIN; ++k) {
            const int r = UR0 + rb + k * RSTRIDE;
            nq[k] = (r < UR1) ? u_point(r, HC0 + cx) : make_uint2(0u, 0u);
        }
        // Extra cols: at most 1 row per thread after the stride math for EXTRA>0
        // (36 rows x 8 cols = 288 <= 512 ; 34 x 4 = 136 <= 512)
        uint2 nqE = make_uint2(0u, 0u);
        const bool doE = (EXTRA > 0) && (rE0 < UR1);
        if (doE) nqE = u_point(rE0, HC0 + cxE);

        __syncthreads();   // everyone done READING sQ/sH

        #pragma unroll
        for (int k = 0; k < NMAIN; ++k) {
            const int r = UR0 + rb + k * RSTRIDE;
            if (r < UR1) sQ[r * EX + HC0 + cx] = nq[k];
        }
        if (doE)
            sQ[rE0 * EX + HC0 + cxE] = nqE;

        __syncthreads();   // writes visible before next iteration reads
    }
}

// ============================================================================
// Fused kernel: 3 CRF iterations, single fp16 Q buffer + H scratch in smem.
// ============================================================================
__global__ __launch_bounds__(NTHREADS, 2)
void crf_fused(const float* __restrict__ unary,
               const float* __restrict__ wapp,
               const float* __restrict__ wsmo,
               const float* __restrict__ compat,
               float*       __restrict__ out)
{
    extern __shared__ uint2 smem[];
    uint2* sQ = smem;
    uint2* sH = smem + NEXT;

    const int b   = blockIdx.z;
    const int ty0 = blockIdx.y * TY;
    const int tx0 = blockIdx.x * TX;
    const int tid = threadIdx.x;

    // Uniform parameters -> packed half2 (independent of crf_setup)
    const __half2 w1h  = __float2half2_rn(W1f);
    const __half2 w4h  = __float2half2_rn(W4f);
    const __half2 wa01 = __floats2half2_rn(wapp[0], wapp[1]);
    const __half2 wa23 = __floats2half2_rn(wapp[2], wapp[3]);
    const __half2 ws01 = __floats2half2_rn(wsmo[0], wsmo[1]);
    const __half2 ws23 = __floats2half2_rn(wsmo[2], wsmo[3]);
    const __half2 ccA0 = __floats2half2_rn(compat[0],  compat[4]);
    const __half2 ccA1 = __floats2half2_rn(compat[1],  compat[5]);
    const __half2 ccA2 = __floats2half2_rn(compat[2],  compat[6]);
    const __half2 ccA3 = __floats2half2_rn(compat[3],  compat[7]);
    const __half2 ccB0 = __floats2half2_rn(compat[8],  compat[12]);
    const __half2 ccB1 = __floats2half2_rn(compat[9],  compat[13]);
    const __half2 ccB2 = __floats2half2_rn(compat[10], compat[14]);
    const __half2 ccB3 = __floats2half2_rn(compat[11], compat[15]);

    // ---- Phase 0: softmax(unary) over the full extended tile -> sQ ----
    // (setup-independent; overlaps with crf_setup under PDL)
    for (int i = tid; i < NEXT; i += NTHREADS) {
        const int row = i / EX;
        const int col = i - row * EX;
        const int gy = ty0 + row - 3;
        const int gx = tx0 + col - 6;
        uint2 q = make_uint2(0u, 0u);
        if (gy >= 0 && gy < Hn && gx >= 0 && gx < Wn) {
            const int gg = b * CHWn + gy * Wn + gx;
            const float4 sm = softmax4(make_float4(unary[gg],
                                                   unary[gg + HWn],
                                                   unary[gg + 2 * HWn],
                                                   unary[gg + 3 * HWn]));
            q = make_uint2(h2u(__floats2half2_rn(sm.x, sm.y)),
                           h2u(__floats2half2_rn(sm.z, sm.w)));
        }
        sQ[i] = q;
    }
    __syncthreads();

    crf_do_iter<0, false>(sQ, sH, b, ty0, tx0, tid, unary, out,
                          w1h, w4h, wa01, wa23, ws01, ws23,
                          ccA0, ccA1, ccA2, ccA3, ccB0, ccB1, ccB2, ccB3);
    crf_do_iter<1, false>(sQ, sH, b, ty0, tx0, tid, unary, out,
                          w1h, w4h, wa01, wa23, ws01, ws23,
                          ccA0, ccA1, ccA2, ccA3, ccB0, ccB1, ccB2, ccB3);
    crf_do_iter<2, true >(sQ, sH, b, ty0, tx0, tid, unary, out,
                          w1h, w4h, wa01, wa23, ws01, ws23,
                          ccA0, ccA1, ccA2, ccA3, ccB0, ccB1, ccB2, ccB3);
}

extern "C" void kernel_launch(void* const* d_in, const int* in_sizes, int n_in,
                              void* d_out, int out_size)
{
    const float* unary  = (const float*)d_in[0];
    const float* xyz    = (const float*)d_in[1];
    const float* mask   = (const float*)d_in[2];
    const float* wapp   = (const float*)d_in[3];
    const float* wsmo   = (const float*)d_in[4];
    const float* compat = (const float*)d_in[5];
    float* out = (float*)d_out;

    cudaFuncSetAttribute(crf_fused, cudaFuncAttributeMaxDynamicSharedMemorySize,
                         SMEM_BYTES);

    // Setup (primary) — triggers programmatic completion at block entry.
    dim3 sgrid(Wn / TX, Hn / STY, Bn);
    crf_setup<<<sgrid, SNT>>>(xyz, mask);

    // Fused (secondary) with programmatic dependent launch.
    dim3 grid(Wn / TX, Hn / TY, Bn);

    cudaLaunchConfig_t cfg = {};
    cfg.gridDim = grid;
    cfg.blockDim = dim3(NTHREADS);
    cfg.dynamicSmemBytes = SMEM_BYTES;
    cfg.stream = 0;   // same (legacy default) stream as crf_setup

    cudaLaunchAttribute attrs[1];
    attrs[0].id = cudaLaunchAttributeProgrammaticStreamSerialization;
    attrs[0].val.programmaticStreamSerializationAllowed = 1;
    cfg.attrs = attrs;
    cfg.numAttrs = 1;

    cudaLaunchKernelEx(&cfg, crf_fused, unary, wapp, wsmo, compat, out);
}

// round 17
// speedup vs baseline: 2.2791x; 1.0374x over previous
#include <cuda_runtime.h>
#include <cuda_fp16.h>

// Problem constants
#define Bn 8
#define Hn 64
#define Wn 2048
#define HWn (Hn * Wn)          // 131072
#define CHWn (4 * HWn)         // 524288

// Fused-kernel tile: 128x32 output, +-6 x / +-3 y halo for 3 iterations
#define TX 128
#define TY 32
#define EX 140
#define EY 38
#define NEXT (EX * EY)         // 5320
#define NTHREADS 512           // 2 blocks/SM, RF-exact, single wave (256<=296)

// Setup-kernel tile (single-iteration halo)
#define STY 16
#define SNT 256
#define SHX (TX + 4)           // 132
#define SHY (STY + 2)          // 18
#define SHALO (SHX * SHY)      // 2376

// Separable Gaussian weights: exp(-d^2/(2*0.9^2)) for d=1,2
#define W1f 0.53940751f
#define W4f 0.08465798f

// C2 = -1/(2*0.015^2) * log2(e)
#define C2f      (-3206.0005353f)
#define NEG2C2f  (6412.0010706f)
#define L2Ef     (1.4426950408889634f)
#define MASK_BIG (1.0e9f)
#define SKIP_THR (-40.0f)

// 2 smem buffers (sQ in-place updated via register staging)
#define SMEM_BYTES (2 * NEXT * (int)sizeof(uint2))   // 85120 -> 2 blocks/SM

// Iteration-invariant appearance data (allocation forbidden -> device globals)
__device__ unsigned char g_alive[Bn * HWn];
__device__ float         g_beta[Bn * HWn * 14];

// ---- helpers ----
__device__ __forceinline__ float ex2(float x) {
    float r;
    asm("ex2.approx.ftz.f32 %0, %1;" : "=f"(r) : "f"(x));
    return r;
}
__device__ __forceinline__ __half2 u2h(unsigned u) {
    __half2 h;
    *reinterpret_cast<unsigned*>(&h) = u;
    return h;
}
__device__ __forceinline__ unsigned h2u(__half2 h) {
    return *reinterpret_cast<unsigned*>(&h);
}
// Softmax without max-subtraction: |q| <= ~8 here, far from fp32 exp2 limits.
__device__ __forceinline__ float4 softmax4(float4 q) {
    const float p0 = ex2(q.x * L2Ef);
    const float p1 = ex2(q.y * L2Ef);
    const float p2 = ex2(q.z * L2Ef);
    const float p3 = ex2(q.w * L2Ef);
    const float inv = __fdividef(1.0f, p0 + p1 + p2 + p3);
    return make_float4(p0 * inv, p1 * inv, p2 * inv, p3 * inv);
}

// ============================================================================
// Setup: per-pixel alive flag + (rare) exact beta taps. Iteration-invariant.
// ============================================================================
__global__ __launch_bounds__(SNT)
void crf_setup(const float* __restrict__ xyz,
               const float* __restrict__ mask)
{
    // PDL: allow dependent crf_fused to start its setup-independent prologue.
    cudaTriggerProgrammaticLaunchCompletion();

    __shared__ float4 sG[SHALO];

    const int b   = blockIdx.z;
    const int ty0 = blockIdx.y * STY;
    const int tx0 = blockIdx.x * TX;
    const int tid = threadIdx.x;

    const float* __restrict__ Xb = xyz  + b * 3 * HWn;
    const float* __restrict__ Mb = mask + b * HWn;

    for (int i = tid; i < SHALO; i += SNT) {
        const int hy = i / SHX;
        const int hx = i - hy * SHX;
        const int gy = ty0 + hy - 1;
        const int gx = tx0 + hx - 2;
        float4 sg = make_float4(0.f, 0.f, 0.f, -MASK_BIG);
        if (gy >= 0 && gy < Hn && gx >= 0 && gx < Wn) {
            const int g = gy * Wn + gx;
            const float x = Xb[g];
            const float y = Xb[g + HWn];
            const float z = Xb[g + 2 * HWn];
            const float m = Mb[g];
            float nrm = x * x;
            nrm = fmaf(y, y, nrm);
            nrm = fmaf(z, z, nrm);
            sg.x = x; sg.y = y; sg.z = z;
            sg.w = fmaf(nrm, C2f, fmaf(m, MASK_BIG, -MASK_BIG));
        }
        sG[i] = sg;
    }
    __syncthreads();

    const int offs[14] = {
        -SHX - 2, -SHX - 1, -SHX, -SHX + 1, -SHX + 2,
               -2,       -1,            1,        2,
         SHX - 2,  SHX - 1,  SHX,  SHX + 1,  SHX + 2
    };

    for (int k = 0; k < (TX * STY) / SNT; ++k) {
        const int p  = tid + k * SNT;
        const int ty = p >> 7;
        const int tx = p & (TX - 1);
        const int base = (ty + 1) * SHX + (tx + 2);

        const float4 ga = sG[base];
        const float axs = ga.x * NEG2C2f;
        const float ays = ga.y * NEG2C2f;
        const float azs = ga.z * NEG2C2f;
        const float na  = ga.w;

        float maxa = -MASK_BIG;
        #pragma unroll
        for (int t = 0; t < 14; ++t) {
            const float4 gn = sG[base + offs[t]];
            const float arg = fmaf(gn.x, axs,
                              fmaf(gn.y, ays,
                              fmaf(gn.z, azs, gn.w + na)));
            maxa = fmaxf(maxa, arg);
        }

        const bool alive = (maxa > SKIP_THR) && (na > -1.0e8f);
        const int pix = b * HWn + (ty0 + ty) * Wn + (tx0 + tx);
        g_alive[pix] = alive ? 1 : 0;

        if (alive) {
            #pragma unroll
            for (int t = 0; t < 14; ++t) {
                const float4 gn = sG[base + offs[t]];
                const float arg = fmaf(gn.x, axs,
                                  fmaf(gn.y, ays,
                                  fmaf(gn.z, azs, gn.w + na)));
                g_beta[pix * 14 + t] = ex2(arg);
            }
        }
    }
}

// ============================================================================
// One in-smem CRF iteration. Paired H-pass; V-pass with incremental indexing
// and fp16 register staging, written in place into sQ.
// ============================================================================
template<int IT, bool LAST>
__device__ __forceinline__ void crf_do_iter(
    uint2* __restrict__ sQ, uint2* __restrict__ sH,
    const int b, const int ty0, const int tx0, const int tid,
    const float* __restrict__ unary, float* __restrict__ out,
    const __half2 w1h, const __half2 w4h,
    const __half2 wa01, const __half2 wa23,
    const __half2 ws01, const __half2 ws23,
    const __half2 ccA0, const __half2 ccA1, const __half2 ccA2, const __half2 ccA3,
    const __half2 ccB0, const __half2 ccB1, const __half2 ccB2, const __half2 ccB3)
{
    constexpr int HR0 = IT, HR1 = EY - IT;
    constexpr int HC0 = 2 * IT + 2;
    constexpr int HWID = EX - 4 - 4 * IT;   // 136 / 132 / 128
    constexpr int EP   = HWID / 2 - 64;     // 4 / 2 / 0 extra pairs per row
    constexpr int LOG2EP = (EP == 4) ? 2 : 1;
    constexpr int EXTRA = HWID - 128;       // 8 / 4 / 0 (scalar V extra cols)
    constexpr int SHV   = (EXTRA == 8) ? 3 : 2;
    constexpr int UR0 = IT + 1, UR1 = EY - 1 - IT;
    constexpr int UROWS = UR1 - UR0;        // 36 / 34 / 32
    constexpr int NMAIN = (UROWS + 3) / 4;  // 9 / 9 / 8
    constexpr bool EXACT = (NMAIN * 4 == UROWS);  // true / false / true

    // ---- Horizontal 5-tap pass on point pairs (incremental addressing) ----
    auto h_pair = [&](int c) {   // c even: points c, c+1
        const uint4 A = *reinterpret_cast<const uint4*>(&sQ[c - 2]);
        const uint4 B = *reinterpret_cast<const uint4*>(&sQ[c]);
        const uint4 C = *reinterpret_cast<const uint4*>(&sQ[c + 2]);
        const __half2 h00 = __hfma2(w4h, __hadd2(u2h(A.x), u2h(C.x)),
                            __hfma2(w1h, __hadd2(u2h(A.z), u2h(B.z)), u2h(B.x)));
        const __half2 h01 = __hfma2(w4h, __hadd2(u2h(A.y), u2h(C.y)),
                            __hfma2(w1h, __hadd2(u2h(A.w), u2h(B.w)), u2h(B.y)));
        const __half2 h10 = __hfma2(w4h, __hadd2(u2h(A.z), u2h(C.z)),
                            __hfma2(w1h, __hadd2(u2h(B.x), u2h(C.x)), u2h(B.z)));
        const __half2 h11 = __hfma2(w4h, __hadd2(u2h(A.w), u2h(C.w)),
                            __hfma2(w1h, __hadd2(u2h(B.y), u2h(C.y)), u2h(B.w)));
        *reinterpret_cast<uint4*>(&sH[c]) =
            make_uint4(h2u(h00), h2u(h01), h2u(h10), h2u(h11));
    };

    {
        const int r0 = HR0 + (tid >> 6);
        int c = r0 * EX + HC0 + 2 * (tid & 63);
        for (int r = r0; r < HR1; r += NTHREADS >> 6, c += (NTHREADS >> 6) * EX)
            h_pair(c);
        if (EP > 0) {
            const int r1 = HR0 + (tid >> LOG2EP);
            int c2 = r1 * EX + HC0 + 2 * (64 + (tid & (EP - 1)));
            for (int r = r1; r < HR1;
                 r += NTHREADS >> LOG2EP, c2 += (NTHREADS >> LOG2EP) * EX)
                h_pair(c2);
        }
    }
    __syncthreads();

    // PDL: first consumption of g_alive / g_beta happens in iter-0 V-pass.
    if (IT == 0) cudaGridDependencySynchronize();

    // ---- Vertical 3-tap + update (incremental; x-bounds hoisted) ----
    // inb: whether this point maps to a valid global pixel (x already checked)
    auto u_point = [&](int c, int pix, int gg, bool inb) -> uint2 {
        if (!LAST && !inb) return make_uint2(0u, 0u);

        const unsigned char alive = g_alive[pix];

        const uint2 hm = sH[c - EX];
        const uint2 h0 = sH[c];
        const uint2 hp = sH[c + EX];
        const uint2 qc = sQ[c];

        // S = H0 + W1*(Hm+Hp) - Qc
        const __half2 s01 = __hsub2(
            __hfma2(w1h, __hadd2(u2h(hm.x), u2h(hp.x)), u2h(h0.x)), u2h(qc.x));
        const __half2 s23 = __hsub2(
            __hfma2(w1h, __hadd2(u2h(hm.y), u2h(hp.y)), u2h(h0.y)), u2h(qc.y));

        __half2 a01 = __float2half2_rn(0.f);
        __half2 a23 = a01;
        if (alive) {
            const float* __restrict__ bp = g_beta + (size_t)pix * 14;
            const int offs[14] = {
                -EX - 2, -EX - 1, -EX, -EX + 1, -EX + 2,
                      -2,      -1,           1,       2,
                 EX - 2,  EX - 1,  EX,  EX + 1,  EX + 2
            };
            #pragma unroll
            for (int t = 0; t < 14; ++t) {
                const __half2 bmh = __float2half2_rn(bp[t]);
                const uint2 q = sQ[c + offs[t]];
                a01 = __hfma2(bmh, u2h(q.x), a01);
                a23 = __hfma2(bmh, u2h(q.y), a23);
            }
        }

        const __half2 wk01 = __hmul2(s01, __hfma2(wa01, a01, ws01));
        const __half2 wk23 = __hmul2(s23, __hfma2(wa23, a23, ws23));

        // pairwise: depth-3 trees (2 parallel FMA branches + HADD2)
        const __half2 pw01 = __hadd2(
            __hfma2(__high2half2(wk01), ccA1, __hmul2(__low2half2(wk01), ccA0)),
            __hfma2(__high2half2(wk23), ccA3, __hmul2(__low2half2(wk23), ccA2)));
        const __half2 pw23 = __hadd2(
            __hfma2(__high2half2(wk01), ccB1, __hmul2(__low2half2(wk01), ccB0)),
            __hfma2(__high2half2(wk23), ccB3, __hmul2(__low2half2(wk23), ccB2)));

        const float2 p01 = __half22float2(pw01);
        const float2 p23 = __half22float2(pw23);

        const float r0 = unary[gg]           - p01.x;
        const float r1 = unary[gg + HWn]     - p01.y;
        const float r2 = unary[gg + 2 * HWn] - p23.x;
        const float r3 = unary[gg + 3 * HWn] - p23.y;

        if (LAST) {
            out[gg]           = r0;
            out[gg + HWn]     = r1;
            out[gg + 2 * HWn] = r2;
            out[gg + 3 * HWn] = r3;
            return make_uint2(0u, 0u);
        } else {
            const float4 sm = softmax4(make_float4(r0, r1, r2, r3));
            return make_uint2(h2u(__floats2half2_rn(sm.x, sm.y)),
                              h2u(__floats2half2_rn(sm.z, sm.w)));
        }
    };

    // Main columns: column fixed per thread -> x-bounds checked once.
    const int cx  = tid & 127;
    const int rb  = tid >> 7;              // 0..3 row phase
    const int col = HC0 + cx;
    const int gx  = tx0 + col - 6;
    const bool xin = (gx >= 0 && gx < Wn);

    const int r0v  = UR0 + rb;
    const int gy0  = ty0 + r0v - 3;
    const int c0   = r0v * EX + col;
    const int g0   = gy0 * Wn + gx;        // valid only if xin (used guarded)
    const int pix0 = b * HWn + g0;
    const int gg0  = b * CHWn + g0;

    // Extra columns (EXTRA>0): one point per thread.
    const int cxE  = 128 + (tid & (EXTRA > 0 ? (EXTRA - 1) : 0));
    const int rE0  = UR0 + (tid >> SHV);
    const int colE = HC0 + cxE;

    if (LAST) {
        int c = c0, gy = gy0, pixv = pix0, ggv = gg0;
        #pragma unroll
        for (int k = 0; k < NMAIN; ++k) {
            const bool rv = EXACT || (r0v + 4 * k < UR1);
            const bool inb = xin && (gy >= 0) && (gy < Hn);
            if (rv && inb) (void)u_point(c, pixv, ggv, true);
            c += 4 * EX; gy += 4; pixv += 4 * Wn; ggv += 4 * Wn;
        }
        if (EXTRA > 0 && rE0 < UR1) {
            const int gyE = ty0 + rE0 - 3;
            const int gxE = tx0 + colE - 6;
            if (gyE >= 0 && gyE < Hn && gxE >= 0 && gxE < Wn) {
                const int gE = gyE * Wn + gxE;
                (void)u_point(rE0 * EX + colE, b * HWn + gE, b * CHWn + gE, true);
            }
        }
    } else {
        uint2 nq[NMAIN];
        {
            int c = c0, gy = gy0, pixv = pix0, ggv = gg0;
            #pragma unroll
            for (int k = 0; k < NMAIN; ++k) {
                const bool rv = EXACT || (r0v + 4 * k < UR1);
                const bool inb = xin && (gy >= 0) && (gy < Hn);
                nq[k] = rv ? u_point(c, pixv, ggv, inb) : make_uint2(0u, 0u);
                c += 4 * EX; gy += 4; pixv += 4 * Wn; ggv += 4 * Wn;
            }
        }
        uint2 nqE = make_uint2(0u, 0u);
        const bool doE = (EXTRA > 0) && (rE0 < UR1);
        if (doE) {
            const int gyE = ty0 + rE0 - 3;
            const int gxE = tx0 + colE - 6;
            const bool inbE = (gyE >= 0 && gyE < Hn && gxE >= 0 && gxE < Wn);
            const int gE = gyE * Wn + gxE;
            nqE = u_point(rE0 * EX + colE, b * HWn + gE, b * CHWn + gE, inbE);
        }

        __syncthreads();   // everyone done READING sQ/sH

        {
            int c = c0;
            #pragma unroll
            for (int k = 0; k < NMAIN; ++k) {
                const bool rv = EXACT || (r0v + 4 * k < UR1);
                if (rv) sQ[c] = nq[k];
                c += 4 * EX;
            }
        }
        if (doE) sQ[rE0 * EX + colE] = nqE;

        __syncthreads();   // writes visible before next iteration reads
    }
}

// ============================================================================
// Fused kernel: 3 CRF iterations, single fp16 Q buffer + H scratch in smem.
// ============================================================================
__global__ __launch_bounds__(NTHREADS, 2)
void crf_fused(const float* __restrict__ unary,
               const float* __restrict__ wapp,
               const float* __restrict__ wsmo,
               const float* __restrict__ compat,
               float*       __restrict__ out)
{
    extern __shared__ uint2 smem[];
    uint2* sQ = smem;
    uint2* sH = smem + NEXT;

    const int b   = blockIdx.z;
    const int ty0 = blockIdx.y * TY;
    const int tx0 = blockIdx.x * TX;
    const int tid = threadIdx.x;

    // Uniform parameters -> packed half2 (independent of crf_setup)
    const __half2 w1h  = __float2half2_rn(W1f);
    const __half2 w4h  = __float2half2_rn(W4f);
    const __half2 wa01 = __floats2half2_rn(wapp[0], wapp[1]);
    const __half2 wa23 = __floats2half2_rn(wapp[2], wapp[3]);
    const __half2 ws01 = __floats2half2_rn(wsmo[0], wsmo[1]);
    const __half2 ws23 = __floats2half2_rn(wsmo[2], wsmo[3]);
    const __half2 ccA0 = __floats2half2_rn(compat[0],  compat[4]);
    const __half2 ccA1 = __floats2half2_rn(compat[1],  compat[5]);
    const __half2 ccA2 = __floats2half2_rn(compat[2],  compat[6]);
    const __half2 ccA3 = __floats2half2_rn(compat[3],  compat[7]);
    const __half2 ccB0 = __floats2half2_rn(compat[8],  compat[12]);
    const __half2 ccB1 = __floats2half2_rn(compat[9],  compat[13]);
    const __half2 ccB2 = __floats2half2_rn(compat[10], compat[14]);
    const __half2 ccB3 = __floats2half2_rn(compat[11], compat[15]);

    // ---- Phase 0: softmax(unary) -> sQ (incremental row/col tracking) ----
    {
        int row = tid / EX;                 // one div total
        int col = tid - row * EX;
        for (int i = tid; i < NEXT; i += NTHREADS) {
            const int gy = ty0 + row - 3;
            const int gx = tx0 + col - 6;
            uint2 q = make_uint2(0u, 0u);
            if (gy >= 0 && gy < Hn && gx >= 0 && gx < Wn) {
                const int gg = b * CHWn + gy * Wn + gx;
                const float4 sm = softmax4(make_float4(unary[gg],
                                                       unary[gg + HWn],
                                                       unary[gg + 2 * HWn],
                                                       unary[gg + 3 * HWn]));
                q = make_uint2(h2u(__floats2half2_rn(sm.x, sm.y)),
                               h2u(__floats2half2_rn(sm.z, sm.w)));
            }
            sQ[row * EX + col] = q;
            // advance by NTHREADS = 3*EX + 92
            row += 3; col += NTHREADS - 3 * EX;
            if (col >= EX) { col -= EX; row += 1; }
        }
    }
    __syncthreads();

    crf_do_iter<0, false>(sQ, sH, b, ty0, tx0, tid, unary, out,
                          w1h, w4h, wa01, wa23, ws01, ws23,
                          ccA0, ccA1, ccA2, ccA3, ccB0, ccB1, ccB2, ccB3);
    crf_do_iter<1, false>(sQ, sH, b, ty0, tx0, tid, unary, out,
                          w1h, w4h, wa01, wa23, ws01, ws23,
                          ccA0, ccA1, ccA2, ccA3, ccB0, ccB1, ccB2, ccB3);
    crf_do_iter<2, true >(sQ, sH, b, ty0, tx0, tid, unary, out,
                          w1h, w4h, wa01, wa23, ws01, ws23,
                          ccA0, ccA1, ccA2, ccA3, ccB0, ccB1, ccB2, ccB3);
}

extern "C" void kernel_launch(void* const* d_in, const int* in_sizes, int n_in,
                              void* d_out, int out_size)
{
    const float* unary  = (const float*)d_in[0];
    const float* xyz    = (const float*)d_in[1];
    const float* mask   = (const float*)d_in[2];
    const float* wapp   = (const float*)d_in[3];
    const float* wsmo   = (const float*)d_in[4];
    const float* compat = (const float*)d_in[5];
    float* out = (float*)d_out;

    cudaFuncSetAttribute(crf_fused, cudaFuncAttributeMaxDynamicSharedMemorySize,
                         SMEM_BYTES);

    // Setup (primary) — triggers programmatic completion at block entry.
    dim3 sgrid(Wn / TX, Hn / STY, Bn);
    crf_setup<<<sgrid, SNT>>>(xyz, mask);

    // Fused (secondary) with programmatic dependent launch.
    dim3 grid(Wn / TX, Hn / TY, Bn);

    cudaLaunchConfig_t cfg = {};
    cfg.gridDim = grid;
    cfg.blockDim = dim3(NTHREADS);
    cfg.dynamicSmemBytes = SMEM_BYTES;
    cfg.stream = 0;   // same (legacy default) stream as crf_setup

    cudaLaunchAttribute attrs[1];
    attrs[0].id = cudaLaunchAttributeProgrammaticStreamSerialization;
    attrs[0].val.programmaticStreamSerializationAllowed = 1;
    cfg.attrs = attrs;
    cfg.numAttrs = 1;

    cudaLaunchKernelEx(&cfg, crf_fused, unary, wapp, wsmo, compat, out);
}